// round 2
// baseline (speedup 1.0000x reference)
#include <cuda_runtime.h>
#include <cuda_bf16.h>
#include <cstdint>

#define Vv 32000
#define Hh 256
#define Ss 2048
#define Bb 128
#define BV (Bb*Vv)

// ---------------- scratch (static __device__, no allocation) ----------------
__device__ float g_q[Bb*Hh];
__device__ float g_ctx[Bb*Hh];
__device__ float g_scores[Bb*Ss];
__device__ float g_partM[Bb*4];
__device__ float g_partL[Bb*4];
__device__ float g_ctxPart[Bb*4*Hh];
__device__ float g_gA[Bb*768];
__device__ float g_gB[Bb*768];
__device__ __nv_bfloat16 g_cat[Bb*512];

// ---------------- K0: q[b,h] = sum_k h[b,k] * We[k,h]  (We = attn_W[:,H:]) ----
__global__ void __launch_bounds__(256) q_kernel(const float* __restrict__ hidden,
                                                const float* __restrict__ attnW) {
    int b = blockIdx.x, h = threadIdx.x;
    __shared__ float hs[Hh];
    hs[h] = hidden[b*Hh + h];
    __syncthreads();
    float acc = 0.f;
#pragma unroll 8
    for (int k = 0; k < Hh; k++) acc += hs[k] * attnW[k*(2*Hh) + Hh + h];
    g_q[b*Hh + h] = acc;
}

// ---------------- K1a: flash-style partial attention over an s-chunk --------
// scores[b,s] = enc[s,b,:] . q[b,:]   (the per-b constant from part_h cancels in softmax)
__global__ void __launch_bounds__(512) attn_partial(const float* __restrict__ enc) {
    int b = blockIdx.y, sc = blockIdx.x;         // sc in [0,4): 512 s values each
    int tid = threadIdx.x;
    int w = tid >> 5, lane = tid & 31;
    __shared__ float qs[Hh];
    __shared__ float wm[16], wl[16];
    __shared__ float wctx[16][Hh];
    if (tid < Hh) qs[tid] = g_q[b*Hh + tid];
    __syncthreads();
    float qv[8];
#pragma unroll
    for (int k = 0; k < 8; k++) qv[k] = qs[lane*8 + k];

    const float* encb = enc + (long)b*Hh + (long)sc*512*(Bb*Hh) + lane*8;
    float m = -1e30f, l = 0.f;
    float c[8];
#pragma unroll
    for (int k = 0; k < 8; k++) c[k] = 0.f;

    for (int j0 = 0; j0 < 32; j0 += 4) {
        float e[4][8];
#pragma unroll
        for (int jj = 0; jj < 4; jj++) {
            const float* p = encb + (long)(w + 16*(j0+jj))*(Bb*Hh);
            float4 x0 = *(const float4*)p;
            float4 x1 = *(const float4*)(p+4);
            e[jj][0]=x0.x; e[jj][1]=x0.y; e[jj][2]=x0.z; e[jj][3]=x0.w;
            e[jj][4]=x1.x; e[jj][5]=x1.y; e[jj][6]=x1.z; e[jj][7]=x1.w;
        }
#pragma unroll
        for (int jj = 0; jj < 4; jj++) {
            float part = 0.f;
#pragma unroll
            for (int k = 0; k < 8; k++) part += e[jj][k]*qv[k];
#pragma unroll
            for (int o = 16; o; o >>= 1) part += __shfl_xor_sync(0xffffffffu, part, o);
            if (lane == 0) g_scores[b*Ss + sc*512 + w + 16*(j0+jj)] = part;
            float nm  = fmaxf(m, part);
            float scl = __expf(m - nm);
            float p_  = __expf(part - nm);
            l = l*scl + p_;
#pragma unroll
            for (int k = 0; k < 8; k++) c[k] = c[k]*scl + p_*e[jj][k];
            m = nm;
        }
    }
    if (lane == 0) { wm[w] = m; wl[w] = l; }
#pragma unroll
    for (int k = 0; k < 8; k++) wctx[w][lane*8+k] = c[k];
    __syncthreads();
    if (tid < Hh) {
        float gm = -1e30f;
        for (int i = 0; i < 16; i++) gm = fmaxf(gm, wm[i]);
        float L = 0.f, cv = 0.f;
        for (int i = 0; i < 16; i++) {
            float f = __expf(wm[i] - gm);
            L  += wl[i]*f;
            cv += wctx[i][tid]*f;
        }
        g_ctxPart[(b*4+sc)*Hh + tid] = cv;
        if (tid == 0) { g_partM[b*4+sc] = gm; g_partL[b*4+sc] = L; }
    }
}

// ---------------- K1b: combine 4 partials, write attn_weights + context -----
__global__ void __launch_bounds__(256) attn_combine(float* __restrict__ out) {
    int b = blockIdx.x, tid = threadIdx.x;
    float m0 = g_partM[b*4+0], m1 = g_partM[b*4+1], m2 = g_partM[b*4+2], m3 = g_partM[b*4+3];
    float gm = fmaxf(fmaxf(m0,m1), fmaxf(m2,m3));
    float f0 = __expf(m0-gm), f1 = __expf(m1-gm), f2 = __expf(m2-gm), f3 = __expf(m3-gm);
    float L = g_partL[b*4+0]*f0 + g_partL[b*4+1]*f1 + g_partL[b*4+2]*f2 + g_partL[b*4+3]*f3;
    float cv = g_ctxPart[(b*4+0)*Hh+tid]*f0 + g_ctxPart[(b*4+1)*Hh+tid]*f1
             + g_ctxPart[(b*4+2)*Hh+tid]*f2 + g_ctxPart[(b*4+3)*Hh+tid]*f3;
    g_ctx[b*Hh + tid] = cv / L;
    float invL = 1.f / L;
    for (int s = tid; s < Ss; s += 256)
        out[BV + Bb*Hh + b*Ss + s] = __expf(g_scores[b*Ss+s] - gm) * invL;
}

// ---------------- K2: gate pre-activations gi (A) and gh (B) ---------------
__global__ void __launch_bounds__(256) gates_kernel(const int* __restrict__ ids,
        const float* __restrict__ emb, const float* __restrict__ hidden,
        const float* __restrict__ W_ih, const float* __restrict__ W_hh,
        const float* __restrict__ b_ih, const float* __restrict__ b_hh) {
    int r = blockIdx.x >> 1, bh = blockIdx.x & 1;   // r: i-chunk of 8 rows
    int tid = threadIdx.x;
    __shared__ float Wi[8*512];
    __shared__ float Wh[8*256];
    {
        const float4* src = (const float4*)(W_ih + r*8*512);
        float4* dst = (float4*)Wi;
        for (int t = tid; t < 1024; t += 256) dst[t] = src[t];
        const float4* src2 = (const float4*)(W_hh + r*8*256);
        float4* dst2 = (float4*)Wh;
        for (int t = tid; t < 512; t += 256) dst2[t] = src2[t];
    }
    __syncthreads();
    for (int oo = tid; oo < 512; oo += 256) {
        int b  = bh*64 + (oo & 63);
        int il = oo >> 6;
        const float* er = emb + (long)ids[b]*Hh;
        const float* cr = g_ctx + b*Hh;
        const float* hr = hidden + b*Hh;
        const float* wi = Wi + il*512;
        const float* wh = Wh + il*256;
        float a = 0.f, bb = 0.f;
#pragma unroll 4
        for (int j = 0; j < 256; j++) {
            a  += er[j]*wi[j] + cr[j]*wi[256+j];
            bb += hr[j]*wh[j];
        }
        int i = r*8 + il;
        g_gA[b*768 + i] = a  + b_ih[i];
        g_gB[b*768 + i] = bb + b_hh[i];
    }
}

// ---------------- K3: GRU combine, write h_new + build bf16 cat ------------
__global__ void __launch_bounds__(256) gru_kernel(const float* __restrict__ hidden,
                                                  float* __restrict__ out) {
    int b = blockIdx.x, t = threadIdx.x;
    float Ar = g_gA[b*768+t],      Br = g_gB[b*768+t];
    float Az = g_gA[b*768+256+t],  Bz = g_gB[b*768+256+t];
    float An = g_gA[b*768+512+t],  Bn = g_gB[b*768+512+t];
    float r  = 1.f/(1.f + __expf(-(Ar+Br)));
    float z  = 1.f/(1.f + __expf(-(Az+Bz)));
    float n  = tanhf(An + r*Bn);
    float h  = hidden[b*Hh + t];
    float hn = (1.f - z)*n + z*h;
    out[BV + b*Hh + t] = hn;
    float ctx = g_ctx[b*Hh + t];
    g_cat[b*512 + t]       = __float2bfloat16(hn);
    g_cat[b*512 + 256 + t] = __float2bfloat16(ctx);
}

// ---------------- K4: logits = cat(128x512) @ out_W(512xV) + out_b ---------
// bf16 mma.m16n8k16, fp32 accumulate. 128x128 tile per block, 250 blocks.
__global__ void __launch_bounds__(256) gemm_logits(const float* __restrict__ outW,
        const float* __restrict__ outb, float* __restrict__ out) {
    __shared__ __nv_bfloat16 As[128*24];   // row stride 24 halves (12 words, conflict-free)
    __shared__ __nv_bfloat16 Bs[128*24];   // stores W^T tile: [v][k]
    int v0  = blockIdx.x * 128;
    int tid = threadIdx.x;
    int w = tid >> 5, lane = tid & 31;
    int g = lane >> 2, i4 = lane & 3;
    float acc[16][4];
#pragma unroll
    for (int nt = 0; nt < 16; nt++) { acc[nt][0]=acc[nt][1]=acc[nt][2]=acc[nt][3]=0.f; }
    int mA = tid >> 1, hf = tid & 1;
    int kk = tid >> 4, vv = (tid & 15) * 8;

    for (int k0 = 0; k0 < 512; k0 += 16) {
        // A tile: 128 m x 16 k bf16
        uint4 av = *(const uint4*)(g_cat + mA*512 + k0 + hf*8);
        *(uint4*)(As + mA*24 + hf*8) = av;
        // B tile: rows k0..k0+15, 128 v fp32 -> bf16, transposed into Bs[v][k]
        const float* srcB = outW + (long)(k0+kk)*Vv + v0 + vv;
        float4 f1 = *(const float4*)srcB;
        float4 f2 = *(const float4*)(srcB+4);
        Bs[(vv+0)*24+kk] = __float2bfloat16(f1.x);
        Bs[(vv+1)*24+kk] = __float2bfloat16(f1.y);
        Bs[(vv+2)*24+kk] = __float2bfloat16(f1.z);
        Bs[(vv+3)*24+kk] = __float2bfloat16(f1.w);
        Bs[(vv+4)*24+kk] = __float2bfloat16(f2.x);
        Bs[(vv+5)*24+kk] = __float2bfloat16(f2.y);
        Bs[(vv+6)*24+kk] = __float2bfloat16(f2.z);
        Bs[(vv+7)*24+kk] = __float2bfloat16(f2.w);
        __syncthreads();

        const uint32_t* Aw = (const uint32_t*)As;
        const uint32_t* Bw = (const uint32_t*)Bs;
        int mr = w*16 + g;
        uint32_t a0 = Aw[mr*12 + i4];
        uint32_t a1 = Aw[(mr+8)*12 + i4];
        uint32_t a2 = Aw[mr*12 + i4 + 4];
        uint32_t a3 = Aw[(mr+8)*12 + i4 + 4];
#pragma unroll
        for (int nt = 0; nt < 16; nt++) {
            int vr = nt*8 + g;
            uint32_t b0 = Bw[vr*12 + i4];
            uint32_t b1 = Bw[vr*12 + i4 + 4];
            asm volatile(
                "mma.sync.aligned.m16n8k16.row.col.f32.bf16.bf16.f32 "
                "{%0,%1,%2,%3}, {%4,%5,%6,%7}, {%8,%9}, {%0,%1,%2,%3};\n"
                : "+f"(acc[nt][0]), "+f"(acc[nt][1]), "+f"(acc[nt][2]), "+f"(acc[nt][3])
                : "r"(a0), "r"(a1), "r"(a2), "r"(a3), "r"(b0), "r"(b1));
        }
        __syncthreads();
    }
    int mr = w*16 + g;
#pragma unroll
    for (int nt = 0; nt < 16; nt++) {
        int v = v0 + nt*8 + 2*i4;
        float ob0 = outb[v], ob1 = outb[v+1];
        float2 r0 = make_float2(acc[nt][0]+ob0, acc[nt][1]+ob1);
        float2 r1 = make_float2(acc[nt][2]+ob0, acc[nt][3]+ob1);
        *(float2*)(out + (long)mr*Vv + v)     = r0;
        *(float2*)(out + (long)(mr+8)*Vv + v) = r1;
    }
}

// ---------------- K5: in-place log_softmax over V per row ------------------
__global__ void __launch_bounds__(256) lse_kernel(float* __restrict__ out) {
    __shared__ float redm[8];
    __shared__ float reds[8];
    int b = blockIdx.x, tid = threadIdx.x;
    float* row = out + (long)b*Vv;
    float mx = -1e30f;
    for (int v = tid; v < Vv; v += 256) mx = fmaxf(mx, row[v]);
#pragma unroll
    for (int o = 16; o; o >>= 1) mx = fmaxf(mx, __shfl_xor_sync(0xffffffffu, mx, o));
    if ((tid & 31) == 0) redm[tid >> 5] = mx;
    __syncthreads();
    float M = -1e30f;
#pragma unroll
    for (int i = 0; i < 8; i++) M = fmaxf(M, redm[i]);
    float s = 0.f;
    for (int v = tid; v < Vv; v += 256) s += __expf(row[v] - M);
#pragma unroll
    for (int o = 16; o; o >>= 1) s += __shfl_xor_sync(0xffffffffu, s, o);
    if ((tid & 31) == 0) reds[tid >> 5] = s;
    __syncthreads();
    float Sx = 0.f;
#pragma unroll
    for (int i = 0; i < 8; i++) Sx += reds[i];
    float lse = M + logf(Sx);
    for (int v = tid; v < Vv; v += 256) row[v] = row[v] - lse;
}

// ---------------- launch ---------------------------------------------------
extern "C" void kernel_launch(void* const* d_in, const int* in_sizes, int n_in,
                              void* d_out, int out_size) {
    (void)in_sizes; (void)n_in; (void)out_size;
    const int*   ids    = (const int*)  d_in[0];
    const float* hidden = (const float*)d_in[1];
    const float* enc    = (const float*)d_in[2];
    const float* emb    = (const float*)d_in[3];
    const float* attnW  = (const float*)d_in[4];
    // d_in[5] = attn_b: its contribution is a per-batch constant in the
    // softmax argument and cancels exactly — unused.
    const float* W_ih   = (const float*)d_in[6];
    const float* W_hh   = (const float*)d_in[7];
    const float* b_ih   = (const float*)d_in[8];
    const float* b_hh   = (const float*)d_in[9];
    const float* outW   = (const float*)d_in[10];
    const float* outb   = (const float*)d_in[11];
    float* out = (float*)d_out;

    q_kernel<<<Bb, 256>>>(hidden, attnW);
    attn_partial<<<dim3(4, Bb), 512>>>(enc);
    attn_combine<<<Bb, 256>>>(out);
    gates_kernel<<<192, 256>>>(ids, emb, hidden, W_ih, W_hh, b_ih, b_hh);
    gru_kernel<<<Bb, 256>>>(hidden, out);
    gemm_logits<<<Vv/128, 256>>>(outW, outb, out);
    lse_kernel<<<Bb, 256>>>(out);
}

// round 6
// speedup vs baseline: 2.8717x; 2.8717x over previous
#include <cuda_runtime.h>
#include <cuda_bf16.h>
#include <cstdint>

#define Vv 32000
#define Hh 256
#define Ss 2048
#define Bb 128
#define BV (Bb*Vv)

// ---------------- scratch (static __device__, no allocation) ----------------
__device__ float g_q[Bb*Hh];
__device__ float g_ctx[Bb*Hh];
__device__ float g_xcat[Bb*512];
__device__ float g_scores[Bb*Ss];
__device__ float g_partM[Bb*4];
__device__ float g_partL[Bb*4];
__device__ float g_ctxPart[Bb*4*Hh];
__device__ float g_gA[Bb*768];
__device__ float g_gB[Bb*768];
__device__ __nv_bfloat16 g_cat[Bb*512];

__device__ __forceinline__ uint32_t tf32u(float x) {
    uint32_t u;
    asm("cvt.rna.tf32.f32 %0, %1;" : "=r"(u) : "f"(x));
    return u;
}

// ---------------- K0: q[b,h] = sum_k h[b,k] * We[k,h]  (We = attn_W[:,H:]) ----
__global__ void __launch_bounds__(256) q_kernel(const float* __restrict__ hidden,
                                                const float* __restrict__ attnW) {
    int b = blockIdx.x, h = threadIdx.x;
    __shared__ float hs[Hh];
    hs[h] = hidden[b*Hh + h];
    __syncthreads();
    float acc = 0.f;
#pragma unroll 8
    for (int k = 0; k < Hh; k++) acc += hs[k] * attnW[k*(2*Hh) + Hh + h];
    g_q[b*Hh + h] = acc;
}

// ---------------- K1a: flash-style partial attention over an s-chunk --------
__global__ void __launch_bounds__(512) attn_partial(const float* __restrict__ enc) {
    int b = blockIdx.y, sc = blockIdx.x;
    int tid = threadIdx.x;
    int w = tid >> 5, lane = tid & 31;
    __shared__ float qs[Hh];
    __shared__ float wm[16], wl[16];
    __shared__ float wctx[16][Hh];
    if (tid < Hh) qs[tid] = g_q[b*Hh + tid];
    __syncthreads();
    float qv[8];
#pragma unroll
    for (int k = 0; k < 8; k++) qv[k] = qs[lane*8 + k];

    const float* encb = enc + (long)b*Hh + (long)sc*512*(Bb*Hh) + lane*8;
    float m = -1e30f, l = 0.f;
    float c[8];
#pragma unroll
    for (int k = 0; k < 8; k++) c[k] = 0.f;

    for (int j0 = 0; j0 < 32; j0 += 4) {
        float e[4][8];
#pragma unroll
        for (int jj = 0; jj < 4; jj++) {
            const float* p = encb + (long)(w + 16*(j0+jj))*(Bb*Hh);
            float4 x0 = *(const float4*)p;
            float4 x1 = *(const float4*)(p+4);
            e[jj][0]=x0.x; e[jj][1]=x0.y; e[jj][2]=x0.z; e[jj][3]=x0.w;
            e[jj][4]=x1.x; e[jj][5]=x1.y; e[jj][6]=x1.z; e[jj][7]=x1.w;
        }
#pragma unroll
        for (int jj = 0; jj < 4; jj++) {
            float part = 0.f;
#pragma unroll
            for (int k = 0; k < 8; k++) part += e[jj][k]*qv[k];
#pragma unroll
            for (int o = 16; o; o >>= 1) part += __shfl_xor_sync(0xffffffffu, part, o);
            if (lane == 0) g_scores[b*Ss + sc*512 + w + 16*(j0+jj)] = part;
            float nm  = fmaxf(m, part);
            float scl = __expf(m - nm);
            float p_  = __expf(part - nm);
            l = l*scl + p_;
#pragma unroll
            for (int k = 0; k < 8; k++) c[k] = c[k]*scl + p_*e[jj][k];
            m = nm;
        }
    }
    if (lane == 0) { wm[w] = m; wl[w] = l; }
#pragma unroll
    for (int k = 0; k < 8; k++) wctx[w][lane*8+k] = c[k];
    __syncthreads();
    if (tid < Hh) {
        float gm = -1e30f;
        for (int i = 0; i < 16; i++) gm = fmaxf(gm, wm[i]);
        float L = 0.f, cv = 0.f;
        for (int i = 0; i < 16; i++) {
            float f = __expf(wm[i] - gm);
            L  += wl[i]*f;
            cv += wctx[i][tid]*f;
        }
        g_ctxPart[(b*4+sc)*Hh + tid] = cv;
        if (tid == 0) { g_partM[b*4+sc] = gm; g_partL[b*4+sc] = L; }
    }
}

// ---------------- K1b: combine partials, write attn_weights + context + xcat
__global__ void __launch_bounds__(256) attn_combine(const int* __restrict__ ids,
                                                    const float* __restrict__ emb,
                                                    float* __restrict__ out) {
    int b = blockIdx.x, tid = threadIdx.x;
    float m0 = g_partM[b*4+0], m1 = g_partM[b*4+1], m2 = g_partM[b*4+2], m3 = g_partM[b*4+3];
    float gm = fmaxf(fmaxf(m0,m1), fmaxf(m2,m3));
    float f0 = __expf(m0-gm), f1 = __expf(m1-gm), f2 = __expf(m2-gm), f3 = __expf(m3-gm);
    float L = g_partL[b*4+0]*f0 + g_partL[b*4+1]*f1 + g_partL[b*4+2]*f2 + g_partL[b*4+3]*f3;
    float cv = g_ctxPart[(b*4+0)*Hh+tid]*f0 + g_ctxPart[(b*4+1)*Hh+tid]*f1
             + g_ctxPart[(b*4+2)*Hh+tid]*f2 + g_ctxPart[(b*4+3)*Hh+tid]*f3;
    float ctx = cv / L;
    g_ctx[b*Hh + tid] = ctx;
    // build xcat = [embedded, context] for the gates GEMM
    g_xcat[b*512 + tid]       = emb[(long)ids[b]*Hh + tid];
    g_xcat[b*512 + 256 + tid] = ctx;
    float invL = 1.f / L;
    for (int s = tid; s < Ss; s += 256)
        out[BV + Bb*Hh + b*Ss + s] = __expf(g_scores[b*Ss+s] - gm) * invL;
}

// ---------------- K2: gates via TF32 tensor-core GEMM ----------------------
// gA = xcat(128x512) @ W_ih^T(512x768),  gB = h(128x256) @ W_hh^T(256x768)
// Block tile: 128(M) x 64(N); grid = 12. 256 threads = 8 warps (4m x 2n).
__global__ void __launch_bounds__(256) gates_mma(const float* __restrict__ hidden,
        const float* __restrict__ W_ih, const float* __restrict__ W_hh,
        const float* __restrict__ b_ih, const float* __restrict__ b_hh) {
    __shared__ uint32_t As[128*36];   // 128 x 32 k-tile, stride 36 (conflict-free)
    __shared__ uint32_t Bs[64*36];    // 64  x 32 k-tile
    int n0  = blockIdx.x * 64;
    int tid = threadIdx.x;
    int w = tid >> 5, lane = tid & 31;
    int wm = (w >> 1) * 32, wn = (w & 1) * 32;
    int g = lane >> 2, i4 = lane & 3;

    float accA[2][4][4];
    float accB[2][4][4];
#pragma unroll
    for (int mt = 0; mt < 2; mt++)
#pragma unroll
        for (int nt = 0; nt < 4; nt++)
#pragma unroll
            for (int c = 0; c < 4; c++) { accA[mt][nt][c] = 0.f; accB[mt][nt][c] = 0.f; }

#define GATES_PHASE(SRC, LD, KTILES, WPTR, ACC)                                       \
    for (int kt = 0; kt < (KTILES); kt++) {                                           \
        int k0 = kt * 32;                                                             \
        _Pragma("unroll")                                                             \
        for (int it = 0; it < 4; it++) {                                              \
            int lin = tid + it*256;                                                   \
            int row = lin >> 3, col = (lin & 7) * 4;                                  \
            float4 v = *(const float4*)((SRC) + (long)row*(LD) + k0 + col);           \
            As[row*36+col+0] = tf32u(v.x); As[row*36+col+1] = tf32u(v.y);             \
            As[row*36+col+2] = tf32u(v.z); As[row*36+col+3] = tf32u(v.w);             \
        }                                                                             \
        _Pragma("unroll")                                                             \
        for (int it = 0; it < 2; it++) {                                              \
            int lin = tid + it*256;                                                   \
            int row = lin >> 3, col = (lin & 7) * 4;                                  \
            float4 v = *(const float4*)((WPTR) + (long)(n0+row)*(LD) + k0 + col);     \
            Bs[row*36+col+0] = tf32u(v.x); Bs[row*36+col+1] = tf32u(v.y);             \
            Bs[row*36+col+2] = tf32u(v.z); Bs[row*36+col+3] = tf32u(v.w);             \
        }                                                                             \
        __syncthreads();                                                              \
        _Pragma("unroll")                                                             \
        for (int ks = 0; ks < 4; ks++) {                                              \
            uint32_t a[2][4];                                                         \
            _Pragma("unroll")                                                         \
            for (int mt = 0; mt < 2; mt++) {                                          \
                int m = wm + mt*16;                                                   \
                a[mt][0] = As[(m+g   )*36 + ks*8 + i4    ];                           \
                a[mt][1] = As[(m+g+8 )*36 + ks*8 + i4    ];                           \
                a[mt][2] = As[(m+g   )*36 + ks*8 + i4 + 4];                           \
                a[mt][3] = As[(m+g+8 )*36 + ks*8 + i4 + 4];                           \
            }                                                                         \
            _Pragma("unroll")                                                         \
            for (int nt = 0; nt < 4; nt++) {                                          \
                uint32_t b0 = Bs[(wn+nt*8+g)*36 + ks*8 + i4    ];                     \
                uint32_t b1 = Bs[(wn+nt*8+g)*36 + ks*8 + i4 + 4];                     \
                _Pragma("unroll")                                                     \
                for (int mt = 0; mt < 2; mt++) {                                      \
                    asm volatile(                                                     \
                        "mma.sync.aligned.m16n8k8.row.col.f32.tf32.tf32.f32 "         \
                        "{%0,%1,%2,%3}, {%4,%5,%6,%7}, {%8,%9}, {%0,%1,%2,%3};\n"     \
                        : "+f"(ACC[mt][nt][0]), "+f"(ACC[mt][nt][1]),                 \
                          "+f"(ACC[mt][nt][2]), "+f"(ACC[mt][nt][3])                  \
                        : "r"(a[mt][0]), "r"(a[mt][1]), "r"(a[mt][2]), "r"(a[mt][3]), \
                          "r"(b0), "r"(b1));                                          \
                }                                                                     \
            }                                                                         \
        }                                                                             \
        __syncthreads();                                                              \
    }

    GATES_PHASE(g_xcat, 512, 16, W_ih, accA)
    GATES_PHASE(hidden, 256,  8, W_hh, accB)
#undef GATES_PHASE

#pragma unroll
    for (int mt = 0; mt < 2; mt++) {
        int m = wm + mt*16 + g;
#pragma unroll
        for (int nt = 0; nt < 4; nt++) {
            int n = n0 + wn + nt*8 + 2*i4;
            float bi0 = b_ih[n], bi1 = b_ih[n+1];
            float bh0 = b_hh[n], bh1 = b_hh[n+1];
            g_gA[(m  )*768 + n  ] = accA[mt][nt][0] + bi0;
            g_gA[(m  )*768 + n+1] = accA[mt][nt][1] + bi1;
            g_gA[(m+8)*768 + n  ] = accA[mt][nt][2] + bi0;
            g_gA[(m+8)*768 + n+1] = accA[mt][nt][3] + bi1;
            g_gB[(m  )*768 + n  ] = accB[mt][nt][0] + bh0;
            g_gB[(m  )*768 + n+1] = accB[mt][nt][1] + bh1;
            g_gB[(m+8)*768 + n  ] = accB[mt][nt][2] + bh0;
            g_gB[(m+8)*768 + n+1] = accB[mt][nt][3] + bh1;
        }
    }
}

// ---------------- K3: GRU combine, write h_new + build bf16 cat ------------
__global__ void __launch_bounds__(256) gru_kernel(const float* __restrict__ hidden,
                                                  float* __restrict__ out) {
    int b = blockIdx.x, t = threadIdx.x;
    float Ar = g_gA[b*768+t],      Br = g_gB[b*768+t];
    float Az = g_gA[b*768+256+t],  Bz = g_gB[b*768+256+t];
    float An = g_gA[b*768+512+t],  Bn = g_gB[b*768+512+t];
    float r  = 1.f/(1.f + __expf(-(Ar+Br)));
    float z  = 1.f/(1.f + __expf(-(Az+Bz)));
    float n  = tanhf(An + r*Bn);
    float h  = hidden[b*Hh + t];
    float hn = (1.f - z)*n + z*h;
    out[BV + b*Hh + t] = hn;
    float ctx = g_ctx[b*Hh + t];
    g_cat[b*512 + t]       = __float2bfloat16(hn);
    g_cat[b*512 + 256 + t] = __float2bfloat16(ctx);
}

// ---------------- K4: logits = cat(128x512) @ out_W(512xV) + out_b ---------
__global__ void __launch_bounds__(256) gemm_logits(const float* __restrict__ outW,
        const float* __restrict__ outb, float* __restrict__ out) {
    __shared__ __nv_bfloat16 As[128*24];
    __shared__ __nv_bfloat16 Bs[128*24];
    int v0  = blockIdx.x * 128;
    int tid = threadIdx.x;
    int w = tid >> 5, lane = tid & 31;
    int g = lane >> 2, i4 = lane & 3;
    float acc[16][4];
#pragma unroll
    for (int nt = 0; nt < 16; nt++) { acc[nt][0]=acc[nt][1]=acc[nt][2]=acc[nt][3]=0.f; }
    int mA = tid >> 1, hf = tid & 1;
    int kk = tid >> 4, vv = (tid & 15) * 8;

    for (int k0 = 0; k0 < 512; k0 += 16) {
        uint4 av = *(const uint4*)(g_cat + mA*512 + k0 + hf*8);
        *(uint4*)(As + mA*24 + hf*8) = av;
        const float* srcB = outW + (long)(k0+kk)*Vv + v0 + vv;
        float4 f1 = *(const float4*)srcB;
        float4 f2 = *(const float4*)(srcB+4);
        Bs[(vv+0)*24+kk] = __float2bfloat16(f1.x);
        Bs[(vv+1)*24+kk] = __float2bfloat16(f1.y);
        Bs[(vv+2)*24+kk] = __float2bfloat16(f1.z);
        Bs[(vv+3)*24+kk] = __float2bfloat16(f1.w);
        Bs[(vv+4)*24+kk] = __float2bfloat16(f2.x);
        Bs[(vv+5)*24+kk] = __float2bfloat16(f2.y);
        Bs[(vv+6)*24+kk] = __float2bfloat16(f2.z);
        Bs[(vv+7)*24+kk] = __float2bfloat16(f2.w);
        __syncthreads();

        const uint32_t* Aw = (const uint32_t*)As;
        const uint32_t* Bw = (const uint32_t*)Bs;
        int mr = w*16 + g;
        uint32_t a0 = Aw[mr*12 + i4];
        uint32_t a1 = Aw[(mr+8)*12 + i4];
        uint32_t a2 = Aw[mr*12 + i4 + 4];
        uint32_t a3 = Aw[(mr+8)*12 + i4 + 4];
#pragma unroll
        for (int nt = 0; nt < 16; nt++) {
            int vr = nt*8 + g;
            uint32_t b0 = Bw[vr*12 + i4];
            uint32_t b1 = Bw[vr*12 + i4 + 4];
            asm volatile(
                "mma.sync.aligned.m16n8k16.row.col.f32.bf16.bf16.f32 "
                "{%0,%1,%2,%3}, {%4,%5,%6,%7}, {%8,%9}, {%0,%1,%2,%3};\n"
                : "+f"(acc[nt][0]), "+f"(acc[nt][1]), "+f"(acc[nt][2]), "+f"(acc[nt][3])
                : "r"(a0), "r"(a1), "r"(a2), "r"(a3), "r"(b0), "r"(b1));
        }
        __syncthreads();
    }
    int mr = w*16 + g;
#pragma unroll
    for (int nt = 0; nt < 16; nt++) {
        int v = v0 + nt*8 + 2*i4;
        float ob0 = outb[v], ob1 = outb[v+1];
        float2 r0 = make_float2(acc[nt][0]+ob0, acc[nt][1]+ob1);
        float2 r1 = make_float2(acc[nt][2]+ob0, acc[nt][3]+ob1);
        *(float2*)(out + (long)mr*Vv + v)     = r0;
        *(float2*)(out + (long)(mr+8)*Vv + v) = r1;
    }
}

// ---------------- K5: in-place log_softmax over V per row ------------------
__global__ void __launch_bounds__(256) lse_kernel(float* __restrict__ out) {
    __shared__ float redm[8];
    __shared__ float reds[8];
    int b = blockIdx.x, tid = threadIdx.x;
    float* row = out + (long)b*Vv;
    float mx = -1e30f;
    for (int v = tid; v < Vv; v += 256) mx = fmaxf(mx, row[v]);
#pragma unroll
    for (int o = 16; o; o >>= 1) mx = fmaxf(mx, __shfl_xor_sync(0xffffffffu, mx, o));
    if ((tid & 31) == 0) redm[tid >> 5] = mx;
    __syncthreads();
    float M = -1e30f;
#pragma unroll
    for (int i = 0; i < 8; i++) M = fmaxf(M, redm[i]);
    float s = 0.f;
    for (int v = tid; v < Vv; v += 256) s += __expf(row[v] - M);
#pragma unroll
    for (int o = 16; o; o >>= 1) s += __shfl_xor_sync(0xffffffffu, s, o);
    if ((tid & 31) == 0) reds[tid >> 5] = s;
    __syncthreads();
    float Sx = 0.f;
#pragma unroll
    for (int i = 0; i < 8; i++) Sx += reds[i];
    float lse = M + logf(Sx);
    for (int v = tid; v < Vv; v += 256) row[v] = row[v] - lse;
}

// ---------------- launch ---------------------------------------------------
extern "C" void kernel_launch(void* const* d_in, const int* in_sizes, int n_in,
                              void* d_out, int out_size) {
    (void)in_sizes; (void)n_in; (void)out_size;
    const int*   ids    = (const int*)  d_in[0];
    const float* hidden = (const float*)d_in[1];
    const float* enc    = (const float*)d_in[2];
    const float* emb    = (const float*)d_in[3];
    const float* attnW  = (const float*)d_in[4];
    // d_in[5] = attn_b: per-batch constant in softmax argument — cancels.
    const float* W_ih   = (const float*)d_in[6];
    const float* W_hh   = (const float*)d_in[7];
    const float* b_ih   = (const float*)d_in[8];
    const float* b_hh   = (const float*)d_in[9];
    const float* outW   = (const float*)d_in[10];
    const float* outb   = (const float*)d_in[11];
    float* out = (float*)d_out;

    q_kernel<<<Bb, 256>>>(hidden, attnW);
    attn_partial<<<dim3(4, Bb), 512>>>(enc);
    attn_combine<<<Bb, 256>>>(ids, emb, out);
    gates_mma<<<12, 256>>>(hidden, W_ih, W_hh, b_ih, b_hh);
    gru_kernel<<<Bb, 256>>>(hidden, out);
    gemm_logits<<<Vv/128, 256>>>(outW, outb, out);
    lse_kernel<<<Bb, 256>>>(out);
}

// round 7
// speedup vs baseline: 3.0718x; 1.0697x over previous
#include <cuda_runtime.h>
#include <cuda_bf16.h>
#include <cstdint>

#define Vv 32000
#define Hh 256
#define Ss 2048
#define Bb 128
#define BV (Bb*Vv)

// ---------------- scratch (static __device__, no allocation) ----------------
__device__ float g_q[Bb*Hh];
__device__ float g_ctx[Bb*Hh];
__device__ float g_xcat[Bb*512];
__device__ float g_scores[Bb*Ss];
__device__ float g_partM[Bb*4];
__device__ float g_partL[Bb*4];
__device__ float g_ctxPart[Bb*4*Hh];
__device__ float g_gA[Bb*768];
__device__ float g_gB[Bb*768];
__device__ __nv_bfloat16 g_cat[Bb*512];

__device__ __forceinline__ uint32_t tf32u(float x) {
    uint32_t u;
    asm("cvt.rna.tf32.f32 %0, %1;" : "=r"(u) : "f"(x));
    return u;
}

// ---------------- K0: q[b,h] = sum_k h[b,k] * We[k,h]  (We = attn_W[:,H:]) ----
__global__ void __launch_bounds__(256) q_kernel(const float* __restrict__ hidden,
                                                const float* __restrict__ attnW) {
    int b = blockIdx.x, h = threadIdx.x;
    __shared__ float hs[Hh];
    hs[h] = hidden[b*Hh + h];
    __syncthreads();
    float acc = 0.f;
#pragma unroll 8
    for (int k = 0; k < Hh; k++) acc += hs[k] * attnW[k*(2*Hh) + Hh + h];
    g_q[b*Hh + h] = acc;
}

// ---------------- K1a: flash-style partial attention over an s-chunk --------
__global__ void __launch_bounds__(512) attn_partial(const float* __restrict__ enc) {
    int b = blockIdx.y, sc = blockIdx.x;
    int tid = threadIdx.x;
    int w = tid >> 5, lane = tid & 31;
    __shared__ float qs[Hh];
    __shared__ float wm[16], wl[16];
    __shared__ float wctx[16][Hh];
    if (tid < Hh) qs[tid] = g_q[b*Hh + tid];
    __syncthreads();
    float qv[8];
#pragma unroll
    for (int k = 0; k < 8; k++) qv[k] = qs[lane*8 + k];

    const float* encb = enc + (long)b*Hh + (long)sc*512*(Bb*Hh) + lane*8;
    float m = -1e30f, l = 0.f;
    float c[8];
#pragma unroll
    for (int k = 0; k < 8; k++) c[k] = 0.f;

    for (int j0 = 0; j0 < 32; j0 += 4) {
        float e[4][8];
#pragma unroll
        for (int jj = 0; jj < 4; jj++) {
            const float* p = encb + (long)(w + 16*(j0+jj))*(Bb*Hh);
            float4 x0 = *(const float4*)p;
            float4 x1 = *(const float4*)(p+4);
            e[jj][0]=x0.x; e[jj][1]=x0.y; e[jj][2]=x0.z; e[jj][3]=x0.w;
            e[jj][4]=x1.x; e[jj][5]=x1.y; e[jj][6]=x1.z; e[jj][7]=x1.w;
        }
#pragma unroll
        for (int jj = 0; jj < 4; jj++) {
            float part = 0.f;
#pragma unroll
            for (int k = 0; k < 8; k++) part += e[jj][k]*qv[k];
#pragma unroll
            for (int o = 16; o; o >>= 1) part += __shfl_xor_sync(0xffffffffu, part, o);
            if (lane == 0) g_scores[b*Ss + sc*512 + w + 16*(j0+jj)] = part;
            float nm  = fmaxf(m, part);
            float scl = __expf(m - nm);
            float p_  = __expf(part - nm);
            l = l*scl + p_;
#pragma unroll
            for (int k = 0; k < 8; k++) c[k] = c[k]*scl + p_*e[jj][k];
            m = nm;
        }
    }
    if (lane == 0) { wm[w] = m; wl[w] = l; }
#pragma unroll
    for (int k = 0; k < 8; k++) wctx[w][lane*8+k] = c[k];
    __syncthreads();
    if (tid < Hh) {
        float gm = -1e30f;
        for (int i = 0; i < 16; i++) gm = fmaxf(gm, wm[i]);
        float L = 0.f, cv = 0.f;
        for (int i = 0; i < 16; i++) {
            float f = __expf(wm[i] - gm);
            L  += wl[i]*f;
            cv += wctx[i][tid]*f;
        }
        g_ctxPart[(b*4+sc)*Hh + tid] = cv;
        if (tid == 0) { g_partM[b*4+sc] = gm; g_partL[b*4+sc] = L; }
    }
}

// ---------------- K1b: combine partials, write attn_weights + context + xcat
__global__ void __launch_bounds__(256) attn_combine(const int* __restrict__ ids,
                                                    const float* __restrict__ emb,
                                                    float* __restrict__ out) {
    int b = blockIdx.x, tid = threadIdx.x;
    float m0 = g_partM[b*4+0], m1 = g_partM[b*4+1], m2 = g_partM[b*4+2], m3 = g_partM[b*4+3];
    float gm = fmaxf(fmaxf(m0,m1), fmaxf(m2,m3));
    float f0 = __expf(m0-gm), f1 = __expf(m1-gm), f2 = __expf(m2-gm), f3 = __expf(m3-gm);
    float L = g_partL[b*4+0]*f0 + g_partL[b*4+1]*f1 + g_partL[b*4+2]*f2 + g_partL[b*4+3]*f3;
    float cv = g_ctxPart[(b*4+0)*Hh+tid]*f0 + g_ctxPart[(b*4+1)*Hh+tid]*f1
             + g_ctxPart[(b*4+2)*Hh+tid]*f2 + g_ctxPart[(b*4+3)*Hh+tid]*f3;
    float ctx = cv / L;
    g_ctx[b*Hh + tid] = ctx;
    g_xcat[b*512 + tid]       = emb[(long)ids[b]*Hh + tid];
    g_xcat[b*512 + 256 + tid] = ctx;
    float invL = 1.f / L;
    for (int s = tid; s < Ss; s += 256)
        out[BV + Bb*Hh + b*Ss + s] = __expf(g_scores[b*Ss+s] - gm) * invL;
}

// ---------------- K2: gates via TF32 tensor-core GEMM (split + pipelined) ---
// phase 0: gA = xcat(128x512) @ W_ih^T   phase 1: gB = h(128x256) @ W_hh^T
// grid = (24, 2): 24 n-tiles of 32, 2 phases. 256 thr = 8 warps (4m x 2n).
// Double-buffered smem, register prefetch, 1 sync per k-tile.
__global__ void __launch_bounds__(256) gates_mma(const float* __restrict__ hidden,
        const float* __restrict__ W_ih, const float* __restrict__ W_hh,
        const float* __restrict__ b_ih, const float* __restrict__ b_hh) {
    __shared__ uint32_t As[2][128*36];
    __shared__ uint32_t Bs[2][32*36];

    int phase = blockIdx.y;
    const float* SRC  = phase ? hidden : g_xcat;
    const float* WPTR = phase ? W_hh   : W_ih;
    const float* bias = phase ? b_hh   : b_ih;
    float*       dst  = phase ? g_gB   : g_gA;
    int LD = phase ? 256 : 512;
    int KT = phase ? 8   : 16;

    int n0  = blockIdx.x * 32;
    int tid = threadIdx.x;
    int w = tid >> 5, lane = tid & 31;
    int wm = (w >> 1) * 32, wn = (w & 1) * 16;
    int g = lane >> 2, i4 = lane & 3;

    int arow = tid >> 3, acol = (tid & 7) * 4;   // +32 rows per it
    int brow = tid >> 3, bcol = (tid & 7) * 4;   // brow 0..31

    float accA[2][2][4];
#pragma unroll
    for (int mt = 0; mt < 2; mt++)
#pragma unroll
        for (int nt = 0; nt < 2; nt++)
#pragma unroll
            for (int c = 0; c < 4; c++) accA[mt][nt][c] = 0.f;

    float4 ra[4]; float4 rb;
    // prologue: load k-tile 0
#pragma unroll
    for (int it = 0; it < 4; it++)
        ra[it] = *(const float4*)(SRC + (long)(arow + it*32)*LD + acol);
    rb = *(const float4*)(WPTR + (long)(n0 + brow)*LD + bcol);
#pragma unroll
    for (int it = 0; it < 4; it++) {
        int r = arow + it*32;
        As[0][r*36+acol+0] = tf32u(ra[it].x); As[0][r*36+acol+1] = tf32u(ra[it].y);
        As[0][r*36+acol+2] = tf32u(ra[it].z); As[0][r*36+acol+3] = tf32u(ra[it].w);
    }
    Bs[0][brow*36+bcol+0] = tf32u(rb.x); Bs[0][brow*36+bcol+1] = tf32u(rb.y);
    Bs[0][brow*36+bcol+2] = tf32u(rb.z); Bs[0][brow*36+bcol+3] = tf32u(rb.w);
    __syncthreads();

    for (int kt = 0; kt < KT; kt++) {
        int cur = kt & 1;
        if (kt + 1 < KT) {
            int k0 = (kt + 1) * 32;
#pragma unroll
            for (int it = 0; it < 4; it++)
                ra[it] = *(const float4*)(SRC + (long)(arow + it*32)*LD + k0 + acol);
            rb = *(const float4*)(WPTR + (long)(n0 + brow)*LD + k0 + bcol);
        }
#pragma unroll
        for (int ks = 0; ks < 4; ks++) {
            uint32_t a[2][4];
#pragma unroll
            for (int mt = 0; mt < 2; mt++) {
                int m = wm + mt*16;
                a[mt][0] = As[cur][(m+g   )*36 + ks*8 + i4    ];
                a[mt][1] = As[cur][(m+g+8 )*36 + ks*8 + i4    ];
                a[mt][2] = As[cur][(m+g   )*36 + ks*8 + i4 + 4];
                a[mt][3] = As[cur][(m+g+8 )*36 + ks*8 + i4 + 4];
            }
#pragma unroll
            for (int nt = 0; nt < 2; nt++) {
                uint32_t b0 = Bs[cur][(wn+nt*8+g)*36 + ks*8 + i4    ];
                uint32_t b1 = Bs[cur][(wn+nt*8+g)*36 + ks*8 + i4 + 4];
#pragma unroll
                for (int mt = 0; mt < 2; mt++) {
                    asm volatile(
                        "mma.sync.aligned.m16n8k8.row.col.f32.tf32.tf32.f32 "
                        "{%0,%1,%2,%3}, {%4,%5,%6,%7}, {%8,%9}, {%0,%1,%2,%3};\n"
                        : "+f"(accA[mt][nt][0]), "+f"(accA[mt][nt][1]),
                          "+f"(accA[mt][nt][2]), "+f"(accA[mt][nt][3])
                        : "r"(a[mt][0]), "r"(a[mt][1]), "r"(a[mt][2]), "r"(a[mt][3]),
                          "r"(b0), "r"(b1));
                }
            }
        }
        if (kt + 1 < KT) {
            int nxt = 1 - cur;
#pragma unroll
            for (int it = 0; it < 4; it++) {
                int r = arow + it*32;
                As[nxt][r*36+acol+0] = tf32u(ra[it].x); As[nxt][r*36+acol+1] = tf32u(ra[it].y);
                As[nxt][r*36+acol+2] = tf32u(ra[it].z); As[nxt][r*36+acol+3] = tf32u(ra[it].w);
            }
            Bs[nxt][brow*36+bcol+0] = tf32u(rb.x); Bs[nxt][brow*36+bcol+1] = tf32u(rb.y);
            Bs[nxt][brow*36+bcol+2] = tf32u(rb.z); Bs[nxt][brow*36+bcol+3] = tf32u(rb.w);
        }
        __syncthreads();
    }

#pragma unroll
    for (int mt = 0; mt < 2; mt++) {
        int m = wm + mt*16 + g;
#pragma unroll
        for (int nt = 0; nt < 2; nt++) {
            int n = n0 + wn + nt*8 + 2*i4;
            float b0 = bias[n], b1 = bias[n+1];
            dst[(m  )*768 + n  ] = accA[mt][nt][0] + b0;
            dst[(m  )*768 + n+1] = accA[mt][nt][1] + b1;
            dst[(m+8)*768 + n  ] = accA[mt][nt][2] + b0;
            dst[(m+8)*768 + n+1] = accA[mt][nt][3] + b1;
        }
    }
}

// ---------------- K3: GRU combine, write h_new + build bf16 cat ------------
__global__ void __launch_bounds__(256) gru_kernel(const float* __restrict__ hidden,
                                                  float* __restrict__ out) {
    int b = blockIdx.x, t = threadIdx.x;
    float Ar = g_gA[b*768+t],      Br = g_gB[b*768+t];
    float Az = g_gA[b*768+256+t],  Bz = g_gB[b*768+256+t];
    float An = g_gA[b*768+512+t],  Bn = g_gB[b*768+512+t];
    float r  = 1.f/(1.f + __expf(-(Ar+Br)));
    float z  = 1.f/(1.f + __expf(-(Az+Bz)));
    float n  = tanhf(An + r*Bn);
    float h  = hidden[b*Hh + t];
    float hn = (1.f - z)*n + z*h;
    out[BV + b*Hh + t] = hn;
    float ctx = g_ctx[b*Hh + t];
    g_cat[b*512 + t]       = __float2bfloat16(hn);
    g_cat[b*512 + 256 + t] = __float2bfloat16(ctx);
}

// ---------------- K4: logits GEMM, double-buffered + register prefetch -----
__global__ void __launch_bounds__(256) gemm_logits(const float* __restrict__ outW,
        const float* __restrict__ outb, float* __restrict__ out) {
    __shared__ __nv_bfloat16 As[2][128*24];
    __shared__ __nv_bfloat16 Bs[2][128*24];
    int v0  = blockIdx.x * 128;
    int tid = threadIdx.x;
    int w = tid >> 5, lane = tid & 31;
    int g = lane >> 2, i4 = lane & 3;
    float acc[16][4];
#pragma unroll
    for (int nt = 0; nt < 16; nt++) { acc[nt][0]=acc[nt][1]=acc[nt][2]=acc[nt][3]=0.f; }
    int mA = tid >> 1, hf = tid & 1;
    int kk = tid >> 4, vv = (tid & 15) * 8;

    uint4 av; float4 f1, f2;
    // prologue: k-tile 0
    av = *(const uint4*)(g_cat + mA*512 + hf*8);
    {
        const float* srcB = outW + (long)kk*Vv + v0 + vv;
        f1 = *(const float4*)srcB; f2 = *(const float4*)(srcB+4);
    }
    *(uint4*)(&As[0][mA*24 + hf*8]) = av;
    Bs[0][(vv+0)*24+kk] = __float2bfloat16(f1.x);
    Bs[0][(vv+1)*24+kk] = __float2bfloat16(f1.y);
    Bs[0][(vv+2)*24+kk] = __float2bfloat16(f1.z);
    Bs[0][(vv+3)*24+kk] = __float2bfloat16(f1.w);
    Bs[0][(vv+4)*24+kk] = __float2bfloat16(f2.x);
    Bs[0][(vv+5)*24+kk] = __float2bfloat16(f2.y);
    Bs[0][(vv+6)*24+kk] = __float2bfloat16(f2.z);
    Bs[0][(vv+7)*24+kk] = __float2bfloat16(f2.w);
    __syncthreads();

    for (int kt = 0; kt < 32; kt++) {
        int cur = kt & 1;
        if (kt < 31) {
            int k0 = (kt + 1) * 16;
            av = *(const uint4*)(g_cat + mA*512 + k0 + hf*8);
            const float* srcB = outW + (long)(k0+kk)*Vv + v0 + vv;
            f1 = *(const float4*)srcB; f2 = *(const float4*)(srcB+4);
        }
        const uint32_t* Aw = (const uint32_t*)As[cur];
        const uint32_t* Bw = (const uint32_t*)Bs[cur];
        int mr = w*16 + g;
        uint32_t a0 = Aw[mr*12 + i4];
        uint32_t a1 = Aw[(mr+8)*12 + i4];
        uint32_t a2 = Aw[mr*12 + i4 + 4];
        uint32_t a3 = Aw[(mr+8)*12 + i4 + 4];
#pragma unroll
        for (int nt = 0; nt < 16; nt++) {
            int vr = nt*8 + g;
            uint32_t b0 = Bw[vr*12 + i4];
            uint32_t b1 = Bw[vr*12 + i4 + 4];
            asm volatile(
                "mma.sync.aligned.m16n8k16.row.col.f32.bf16.bf16.f32 "
                "{%0,%1,%2,%3}, {%4,%5,%6,%7}, {%8,%9}, {%0,%1,%2,%3};\n"
                : "+f"(acc[nt][0]), "+f"(acc[nt][1]), "+f"(acc[nt][2]), "+f"(acc[nt][3])
                : "r"(a0), "r"(a1), "r"(a2), "r"(a3), "r"(b0), "r"(b1));
        }
        if (kt < 31) {
            int nxt = 1 - cur;
            *(uint4*)(&As[nxt][mA*24 + hf*8]) = av;
            Bs[nxt][(vv+0)*24+kk] = __float2bfloat16(f1.x);
            Bs[nxt][(vv+1)*24+kk] = __float2bfloat16(f1.y);
            Bs[nxt][(vv+2)*24+kk] = __float2bfloat16(f1.z);
            Bs[nxt][(vv+3)*24+kk] = __float2bfloat16(f1.w);
            Bs[nxt][(vv+4)*24+kk] = __float2bfloat16(f2.x);
            Bs[nxt][(vv+5)*24+kk] = __float2bfloat16(f2.y);
            Bs[nxt][(vv+6)*24+kk] = __float2bfloat16(f2.z);
            Bs[nxt][(vv+7)*24+kk] = __float2bfloat16(f2.w);
        }
        __syncthreads();
    }
    int mr = w*16 + g;
#pragma unroll
    for (int nt = 0; nt < 16; nt++) {
        int v = v0 + nt*8 + 2*i4;
        float ob0 = outb[v], ob1 = outb[v+1];
        float2 r0 = make_float2(acc[nt][0]+ob0, acc[nt][1]+ob1);
        float2 r1 = make_float2(acc[nt][2]+ob0, acc[nt][3]+ob1);
        *(float2*)(out + (long)mr*Vv + v)     = r0;
        *(float2*)(out + (long)(mr+8)*Vv + v) = r1;
    }
}

// ---------------- K5: in-place log_softmax over V per row ------------------
__global__ void __launch_bounds__(256) lse_kernel(float* __restrict__ out) {
    __shared__ float redm[8];
    __shared__ float reds[8];
    int b = blockIdx.x, tid = threadIdx.x;
    float* row = out + (long)b*Vv;
    float mx = -1e30f;
    for (int v = tid; v < Vv; v += 256) mx = fmaxf(mx, row[v]);
#pragma unroll
    for (int o = 16; o; o >>= 1) mx = fmaxf(mx, __shfl_xor_sync(0xffffffffu, mx, o));
    if ((tid & 31) == 0) redm[tid >> 5] = mx;
    __syncthreads();
    float M = -1e30f;
#pragma unroll
    for (int i = 0; i < 8; i++) M = fmaxf(M, redm[i]);
    float s = 0.f;
    for (int v = tid; v < Vv; v += 256) s += __expf(row[v] - M);
#pragma unroll
    for (int o = 16; o; o >>= 1) s += __shfl_xor_sync(0xffffffffu, s, o);
    if ((tid & 31) == 0) reds[tid >> 5] = s;
    __syncthreads();
    float Sx = 0.f;
#pragma unroll
    for (int i = 0; i < 8; i++) Sx += reds[i];
    float lse = M + logf(Sx);
    for (int v = tid; v < Vv; v += 256) row[v] = row[v] - lse;
}

// ---------------- launch ---------------------------------------------------
extern "C" void kernel_launch(void* const* d_in, const int* in_sizes, int n_in,
                              void* d_out, int out_size) {
    (void)in_sizes; (void)n_in; (void)out_size;
    const int*   ids    = (const int*)  d_in[0];
    const float* hidden = (const float*)d_in[1];
    const float* enc    = (const float*)d_in[2];
    const float* emb    = (const float*)d_in[3];
    const float* attnW  = (const float*)d_in[4];
    // d_in[5] = attn_b: per-batch constant in softmax argument — cancels.
    const float* W_ih   = (const float*)d_in[6];
    const float* W_hh   = (const float*)d_in[7];
    const float* b_ih   = (const float*)d_in[8];
    const float* b_hh   = (const float*)d_in[9];
    const float* outW   = (const float*)d_in[10];
    const float* outb   = (const float*)d_in[11];
    float* out = (float*)d_out;

    q_kernel<<<Bb, 256>>>(hidden, attnW);
    attn_partial<<<dim3(4, Bb), 512>>>(enc);
    attn_combine<<<Bb, 256>>>(ids, emb, out);
    gates_mma<<<dim3(24, 2), 256>>>(hidden, W_ih, W_hh, b_ih, b_hh);
    gru_kernel<<<Bb, 256>>>(hidden, out);
    gemm_logits<<<Vv/128, 256>>>(outW, outb, out);
    lse_kernel<<<Bb, 256>>>(out);
}

// round 8
// speedup vs baseline: 3.3454x; 1.0891x over previous
#include <cuda_runtime.h>
#include <cuda_bf16.h>
#include <cstdint>

#define Vv 32000
#define Hh 256
#define Ss 2048
#define Bb 128
#define BV (Bb*Vv)
#define NBLK 250   // gemm_logits blocks

// ---------------- scratch (static __device__, no allocation) ----------------
__device__ float g_q[Bb*Hh];
__device__ float g_ctx[Bb*Hh];
__device__ float g_xcat[Bb*512];
__device__ float g_scores[Bb*Ss];
__device__ float g_partM[Bb*4];
__device__ float g_partL[Bb*4];
__device__ float g_ctxPart[Bb*4*Hh];
__device__ float g_gAp[4*Bb*768];   // split-K partials (no bias)
__device__ float g_gBp[4*Bb*768];
__device__ float g_pM[Bb*NBLK];     // per-block logit max
__device__ float g_pL[Bb*NBLK];     // per-block sumexp
__device__ __nv_bfloat16 g_cat[Bb*512];

__device__ __forceinline__ uint32_t tf32u(float x) {
    uint32_t u;
    asm("cvt.rna.tf32.f32 %0, %1;" : "=r"(u) : "f"(x));
    return u;
}

// ---------------- K0: q[b,h] = sum_k h[b,k] * We[k,h]  (We = attn_W[:,H:]) ----
__global__ void __launch_bounds__(256) q_kernel(const float* __restrict__ hidden,
                                                const float* __restrict__ attnW) {
    int b = blockIdx.x, h = threadIdx.x;
    __shared__ float hs[Hh];
    hs[h] = hidden[b*Hh + h];
    __syncthreads();
    float acc = 0.f;
#pragma unroll 8
    for (int k = 0; k < Hh; k++) acc += hs[k] * attnW[k*(2*Hh) + Hh + h];
    g_q[b*Hh + h] = acc;
}

// ---------------- K1a: flash-style partial attention over an s-chunk --------
__global__ void __launch_bounds__(512) attn_partial(const float* __restrict__ enc) {
    int b = blockIdx.y, sc = blockIdx.x;
    int tid = threadIdx.x;
    int w = tid >> 5, lane = tid & 31;
    __shared__ float qs[Hh];
    __shared__ float wm[16], wl[16];
    __shared__ float wctx[16][Hh];
    if (tid < Hh) qs[tid] = g_q[b*Hh + tid];
    __syncthreads();
    float qv[8];
#pragma unroll
    for (int k = 0; k < 8; k++) qv[k] = qs[lane*8 + k];

    const float* encb = enc + (long)b*Hh + (long)sc*512*(Bb*Hh) + lane*8;
    float m = -1e30f, l = 0.f;
    float c[8];
#pragma unroll
    for (int k = 0; k < 8; k++) c[k] = 0.f;

    for (int j0 = 0; j0 < 32; j0 += 4) {
        float e[4][8];
#pragma unroll
        for (int jj = 0; jj < 4; jj++) {
            const float* p = encb + (long)(w + 16*(j0+jj))*(Bb*Hh);
            float4 x0 = *(const float4*)p;
            float4 x1 = *(const float4*)(p+4);
            e[jj][0]=x0.x; e[jj][1]=x0.y; e[jj][2]=x0.z; e[jj][3]=x0.w;
            e[jj][4]=x1.x; e[jj][5]=x1.y; e[jj][6]=x1.z; e[jj][7]=x1.w;
        }
#pragma unroll
        for (int jj = 0; jj < 4; jj++) {
            float part = 0.f;
#pragma unroll
            for (int k = 0; k < 8; k++) part += e[jj][k]*qv[k];
#pragma unroll
            for (int o = 16; o; o >>= 1) part += __shfl_xor_sync(0xffffffffu, part, o);
            if (lane == 0) g_scores[b*Ss + sc*512 + w + 16*(j0+jj)] = part;
            float nm  = fmaxf(m, part);
            float scl = __expf(m - nm);
            float p_  = __expf(part - nm);
            l = l*scl + p_;
#pragma unroll
            for (int k = 0; k < 8; k++) c[k] = c[k]*scl + p_*e[jj][k];
            m = nm;
        }
    }
    if (lane == 0) { wm[w] = m; wl[w] = l; }
#pragma unroll
    for (int k = 0; k < 8; k++) wctx[w][lane*8+k] = c[k];
    __syncthreads();
    if (tid < Hh) {
        float gm = -1e30f;
        for (int i = 0; i < 16; i++) gm = fmaxf(gm, wm[i]);
        float L = 0.f, cv = 0.f;
        for (int i = 0; i < 16; i++) {
            float f = __expf(wm[i] - gm);
            L  += wl[i]*f;
            cv += wctx[i][tid]*f;
        }
        g_ctxPart[(b*4+sc)*Hh + tid] = cv;
        if (tid == 0) { g_partM[b*4+sc] = gm; g_partL[b*4+sc] = L; }
    }
}

// ---------------- K1b: combine partials, write attn_weights + context + xcat
__global__ void __launch_bounds__(256) attn_combine(const int* __restrict__ ids,
                                                    const float* __restrict__ emb,
                                                    float* __restrict__ out) {
    int b = blockIdx.x, tid = threadIdx.x;
    float m0 = g_partM[b*4+0], m1 = g_partM[b*4+1], m2 = g_partM[b*4+2], m3 = g_partM[b*4+3];
    float gm = fmaxf(fmaxf(m0,m1), fmaxf(m2,m3));
    float f0 = __expf(m0-gm), f1 = __expf(m1-gm), f2 = __expf(m2-gm), f3 = __expf(m3-gm);
    float L = g_partL[b*4+0]*f0 + g_partL[b*4+1]*f1 + g_partL[b*4+2]*f2 + g_partL[b*4+3]*f3;
    float cv = g_ctxPart[(b*4+0)*Hh+tid]*f0 + g_ctxPart[(b*4+1)*Hh+tid]*f1
             + g_ctxPart[(b*4+2)*Hh+tid]*f2 + g_ctxPart[(b*4+3)*Hh+tid]*f3;
    float ctx = cv / L;
    g_ctx[b*Hh + tid] = ctx;
    g_xcat[b*512 + tid]       = emb[(long)ids[b]*Hh + tid];
    g_xcat[b*512 + 256 + tid] = ctx;
    float invL = 1.f / L;
    for (int s = tid; s < Ss; s += 256)
        out[BV + Bb*Hh + b*Ss + s] = __expf(g_scores[b*Ss+s] - gm) * invL;
}

// ---------------- K2: gates TF32 GEMM, split-K x4 ---------------------------
// grid (24, 2, 4): 24 n-tiles of 32, phase (gi/gh), 4 K-chunks.
// phase 0: K=512 -> 4 chunks of 128.  phase 1: K=256 -> 4 chunks of 64.
// Writes bias-free partials; gru_kernel reduces.
__global__ void __launch_bounds__(256) gates_mma(const float* __restrict__ hidden,
        const float* __restrict__ W_ih, const float* __restrict__ W_hh) {
    __shared__ uint32_t As[2][128*36];
    __shared__ uint32_t Bs[2][32*36];

    int phase = blockIdx.y, z = blockIdx.z;
    const float* SRC  = phase ? hidden : g_xcat;
    const float* WPTR = phase ? W_hh   : W_ih;
    float*       dst  = (phase ? g_gBp : g_gAp) + z*(Bb*768);
    int LD = phase ? 256 : 512;
    int KT = phase ? 2   : 4;          // k-tiles of 32 per chunk
    int kbase = z * KT * 32;

    int n0  = blockIdx.x * 32;
    int tid = threadIdx.x;
    int w = tid >> 5, lane = tid & 31;
    int wm = (w >> 1) * 32, wn = (w & 1) * 16;
    int g = lane >> 2, i4 = lane & 3;

    int arow = tid >> 3, acol = (tid & 7) * 4;
    int brow = tid >> 3, bcol = (tid & 7) * 4;

    float accA[2][2][4];
#pragma unroll
    for (int mt = 0; mt < 2; mt++)
#pragma unroll
        for (int nt = 0; nt < 2; nt++)
#pragma unroll
            for (int c = 0; c < 4; c++) accA[mt][nt][c] = 0.f;

    float4 ra[4]; float4 rb;
#pragma unroll
    for (int it = 0; it < 4; it++)
        ra[it] = *(const float4*)(SRC + (long)(arow + it*32)*LD + kbase + acol);
    rb = *(const float4*)(WPTR + (long)(n0 + brow)*LD + kbase + bcol);
#pragma unroll
    for (int it = 0; it < 4; it++) {
        int r = arow + it*32;
        As[0][r*36+acol+0] = tf32u(ra[it].x); As[0][r*36+acol+1] = tf32u(ra[it].y);
        As[0][r*36+acol+2] = tf32u(ra[it].z); As[0][r*36+acol+3] = tf32u(ra[it].w);
    }
    Bs[0][brow*36+bcol+0] = tf32u(rb.x); Bs[0][brow*36+bcol+1] = tf32u(rb.y);
    Bs[0][brow*36+bcol+2] = tf32u(rb.z); Bs[0][brow*36+bcol+3] = tf32u(rb.w);
    __syncthreads();

    for (int kt = 0; kt < KT; kt++) {
        int cur = kt & 1;
        if (kt + 1 < KT) {
            int k0 = kbase + (kt + 1) * 32;
#pragma unroll
            for (int it = 0; it < 4; it++)
                ra[it] = *(const float4*)(SRC + (long)(arow + it*32)*LD + k0 + acol);
            rb = *(const float4*)(WPTR + (long)(n0 + brow)*LD + k0 + bcol);
        }
#pragma unroll
        for (int ks = 0; ks < 4; ks++) {
            uint32_t a[2][4];
#pragma unroll
            for (int mt = 0; mt < 2; mt++) {
                int m = wm + mt*16;
                a[mt][0] = As[cur][(m+g   )*36 + ks*8 + i4    ];
                a[mt][1] = As[cur][(m+g+8 )*36 + ks*8 + i4    ];
                a[mt][2] = As[cur][(m+g   )*36 + ks*8 + i4 + 4];
                a[mt][3] = As[cur][(m+g+8 )*36 + ks*8 + i4 + 4];
            }
#pragma unroll
            for (int nt = 0; nt < 2; nt++) {
                uint32_t b0 = Bs[cur][(wn+nt*8+g)*36 + ks*8 + i4    ];
                uint32_t b1 = Bs[cur][(wn+nt*8+g)*36 + ks*8 + i4 + 4];
#pragma unroll
                for (int mt = 0; mt < 2; mt++) {
                    asm volatile(
                        "mma.sync.aligned.m16n8k8.row.col.f32.tf32.tf32.f32 "
                        "{%0,%1,%2,%3}, {%4,%5,%6,%7}, {%8,%9}, {%0,%1,%2,%3};\n"
                        : "+f"(accA[mt][nt][0]), "+f"(accA[mt][nt][1]),
                          "+f"(accA[mt][nt][2]), "+f"(accA[mt][nt][3])
                        : "r"(a[mt][0]), "r"(a[mt][1]), "r"(a[mt][2]), "r"(a[mt][3]),
                          "r"(b0), "r"(b1));
                }
            }
        }
        if (kt + 1 < KT) {
            int nxt = 1 - cur;
#pragma unroll
            for (int it = 0; it < 4; it++) {
                int r = arow + it*32;
                As[nxt][r*36+acol+0] = tf32u(ra[it].x); As[nxt][r*36+acol+1] = tf32u(ra[it].y);
                As[nxt][r*36+acol+2] = tf32u(ra[it].z); As[nxt][r*36+acol+3] = tf32u(ra[it].w);
            }
            Bs[nxt][brow*36+bcol+0] = tf32u(rb.x); Bs[nxt][brow*36+bcol+1] = tf32u(rb.y);
            Bs[nxt][brow*36+bcol+2] = tf32u(rb.z); Bs[nxt][brow*36+bcol+3] = tf32u(rb.w);
        }
        __syncthreads();
    }

#pragma unroll
    for (int mt = 0; mt < 2; mt++) {
        int m = wm + mt*16 + g;
#pragma unroll
        for (int nt = 0; nt < 2; nt++) {
            int n = n0 + wn + nt*8 + 2*i4;
            dst[(m  )*768 + n  ] = accA[mt][nt][0];
            dst[(m  )*768 + n+1] = accA[mt][nt][1];
            dst[(m+8)*768 + n  ] = accA[mt][nt][2];
            dst[(m+8)*768 + n+1] = accA[mt][nt][3];
        }
    }
}

// ---------------- K3: GRU combine (reduces split-K partials) ----------------
__global__ void __launch_bounds__(256) gru_kernel(const float* __restrict__ hidden,
        const float* __restrict__ b_ih, const float* __restrict__ b_hh,
        float* __restrict__ out) {
    int b = blockIdx.x, t = threadIdx.x;
#define SUM4(P, IDX) (P[IDX] + P[(Bb*768)+(IDX)] + P[2*(Bb*768)+(IDX)] + P[3*(Bb*768)+(IDX)])
    int i0 = b*768 + t, i1 = i0 + 256, i2 = i0 + 512;
    float Ar = SUM4(g_gAp, i0) + b_ih[t];
    float Az = SUM4(g_gAp, i1) + b_ih[256+t];
    float An = SUM4(g_gAp, i2) + b_ih[512+t];
    float Br = SUM4(g_gBp, i0) + b_hh[t];
    float Bz = SUM4(g_gBp, i1) + b_hh[256+t];
    float Bn = SUM4(g_gBp, i2) + b_hh[512+t];
#undef SUM4
    float r  = 1.f/(1.f + __expf(-(Ar+Br)));
    float z  = 1.f/(1.f + __expf(-(Az+Bz)));
    float n  = tanhf(An + r*Bn);
    float h  = hidden[b*Hh + t];
    float hn = (1.f - z)*n + z*h;
    out[BV + b*Hh + t] = hn;
    float ctx = g_ctx[b*Hh + t];
    g_cat[b*512 + t]       = __float2bfloat16(hn);
    g_cat[b*512 + 256 + t] = __float2bfloat16(ctx);
}

// ---------------- K4: logits GEMM + fused partial log-softmax ---------------
__global__ void __launch_bounds__(256) gemm_logits(const float* __restrict__ outW,
        const float* __restrict__ outb, float* __restrict__ out) {
    __shared__ __nv_bfloat16 As[2][128*24];
    __shared__ __nv_bfloat16 Bs[2][128*24];
    int blk = blockIdx.x;
    int v0  = blk * 128;
    int tid = threadIdx.x;
    int w = tid >> 5, lane = tid & 31;
    int g = lane >> 2, i4 = lane & 3;
    float acc[16][4];
#pragma unroll
    for (int nt = 0; nt < 16; nt++) { acc[nt][0]=acc[nt][1]=acc[nt][2]=acc[nt][3]=0.f; }
    int mA = tid >> 1, hf = tid & 1;
    int kk = tid >> 4, vv = (tid & 15) * 8;

    uint4 av; float4 f1, f2;
    av = *(const uint4*)(g_cat + mA*512 + hf*8);
    {
        const float* srcB = outW + (long)kk*Vv + v0 + vv;
        f1 = *(const float4*)srcB; f2 = *(const float4*)(srcB+4);
    }
    *(uint4*)(&As[0][mA*24 + hf*8]) = av;
    Bs[0][(vv+0)*24+kk] = __float2bfloat16(f1.x);
    Bs[0][(vv+1)*24+kk] = __float2bfloat16(f1.y);
    Bs[0][(vv+2)*24+kk] = __float2bfloat16(f1.z);
    Bs[0][(vv+3)*24+kk] = __float2bfloat16(f1.w);
    Bs[0][(vv+4)*24+kk] = __float2bfloat16(f2.x);
    Bs[0][(vv+5)*24+kk] = __float2bfloat16(f2.y);
    Bs[0][(vv+6)*24+kk] = __float2bfloat16(f2.z);
    Bs[0][(vv+7)*24+kk] = __float2bfloat16(f2.w);
    __syncthreads();

    for (int kt = 0; kt < 32; kt++) {
        int cur = kt & 1;
        if (kt < 31) {
            int k0 = (kt + 1) * 16;
            av = *(const uint4*)(g_cat + mA*512 + k0 + hf*8);
            const float* srcB = outW + (long)(k0+kk)*Vv + v0 + vv;
            f1 = *(const float4*)srcB; f2 = *(const float4*)(srcB+4);
        }
        const uint32_t* Aw = (const uint32_t*)As[cur];
        const uint32_t* Bw = (const uint32_t*)Bs[cur];
        int mr = w*16 + g;
        uint32_t a0 = Aw[mr*12 + i4];
        uint32_t a1 = Aw[(mr+8)*12 + i4];
        uint32_t a2 = Aw[mr*12 + i4 + 4];
        uint32_t a3 = Aw[(mr+8)*12 + i4 + 4];
#pragma unroll
        for (int nt = 0; nt < 16; nt++) {
            int vr = nt*8 + g;
            uint32_t b0 = Bw[vr*12 + i4];
            uint32_t b1 = Bw[vr*12 + i4 + 4];
            asm volatile(
                "mma.sync.aligned.m16n8k16.row.col.f32.bf16.bf16.f32 "
                "{%0,%1,%2,%3}, {%4,%5,%6,%7}, {%8,%9}, {%0,%1,%2,%3};\n"
                : "+f"(acc[nt][0]), "+f"(acc[nt][1]), "+f"(acc[nt][2]), "+f"(acc[nt][3])
                : "r"(a0), "r"(a1), "r"(a2), "r"(a3), "r"(b0), "r"(b1));
        }
        if (kt < 31) {
            int nxt = 1 - cur;
            *(uint4*)(&As[nxt][mA*24 + hf*8]) = av;
            Bs[nxt][(vv+0)*24+kk] = __float2bfloat16(f1.x);
            Bs[nxt][(vv+1)*24+kk] = __float2bfloat16(f1.y);
            Bs[nxt][(vv+2)*24+kk] = __float2bfloat16(f1.z);
            Bs[nxt][(vv+3)*24+kk] = __float2bfloat16(f1.w);
            Bs[nxt][(vv+4)*24+kk] = __float2bfloat16(f2.x);
            Bs[nxt][(vv+5)*24+kk] = __float2bfloat16(f2.y);
            Bs[nxt][(vv+6)*24+kk] = __float2bfloat16(f2.z);
            Bs[nxt][(vv+7)*24+kk] = __float2bfloat16(f2.w);
        }
        __syncthreads();
    }
    int mr = w*16 + g;
    // store logits + per-thread max over this block's 128 columns (2 rows/thread)
    float mx0 = -1e30f, mx1 = -1e30f;
#pragma unroll
    for (int nt = 0; nt < 16; nt++) {
        int v = v0 + nt*8 + 2*i4;
        float ob0 = outb[v], ob1 = outb[v+1];
        float r0 = acc[nt][0]+ob0, r1 = acc[nt][1]+ob1;
        float r2 = acc[nt][2]+ob0, r3 = acc[nt][3]+ob1;
        *(float2*)(out + (long)mr*Vv + v)     = make_float2(r0, r1);
        *(float2*)(out + (long)(mr+8)*Vv + v) = make_float2(r2, r3);
        mx0 = fmaxf(mx0, fmaxf(r0, r1));
        mx1 = fmaxf(mx1, fmaxf(r2, r3));
    }
    float s0 = 0.f, s1 = 0.f;
#pragma unroll
    for (int nt = 0; nt < 16; nt++) {
        int v = v0 + nt*8 + 2*i4;
        float ob0 = outb[v], ob1 = outb[v+1];
        s0 += __expf(acc[nt][0]+ob0-mx0) + __expf(acc[nt][1]+ob1-mx0);
        s1 += __expf(acc[nt][2]+ob0-mx1) + __expf(acc[nt][3]+ob1-mx1);
    }
    // reduce across the 4 i4 lanes (online merge)
#pragma unroll
    for (int o = 1; o <= 2; o <<= 1) {
        float om0 = __shfl_xor_sync(0xffffffffu, mx0, o);
        float os0 = __shfl_xor_sync(0xffffffffu, s0,  o);
        float nm0 = fmaxf(mx0, om0);
        s0 = s0*__expf(mx0-nm0) + os0*__expf(om0-nm0); mx0 = nm0;
        float om1 = __shfl_xor_sync(0xffffffffu, mx1, o);
        float os1 = __shfl_xor_sync(0xffffffffu, s1,  o);
        float nm1 = fmaxf(mx1, om1);
        s1 = s1*__expf(mx1-nm1) + os1*__expf(om1-nm1); mx1 = nm1;
    }
    if (i4 == 0) {
        g_pM[mr*NBLK + blk]     = mx0;  g_pL[mr*NBLK + blk]     = s0;
        g_pM[(mr+8)*NBLK + blk] = mx1;  g_pL[(mr+8)*NBLK + blk] = s1;
    }
}

// ---------------- K5: merge partials + subtract lse (single pass over V) ----
__global__ void __launch_bounds__(256) lse_kernel(float* __restrict__ out) {
    __shared__ float redm[8], reds[8];
    __shared__ float s_lse;
    int b = blockIdx.x, tid = threadIdx.x;
    float m = -1e30f, l = 0.f;
    for (int p = tid; p < NBLK; p += 256) {
        float pm = g_pM[b*NBLK + p], pl = g_pL[b*NBLK + p];
        float nm = fmaxf(m, pm);
        l = l*__expf(m-nm) + pl*__expf(pm-nm);
        m = nm;
    }
#pragma unroll
    for (int o = 16; o; o >>= 1) {
        float om = __shfl_xor_sync(0xffffffffu, m, o);
        float ol = __shfl_xor_sync(0xffffffffu, l, o);
        float nm = fmaxf(m, om);
        l = l*__expf(m-nm) + ol*__expf(om-nm);
        m = nm;
    }
    if ((tid & 31) == 0) { redm[tid>>5] = m; reds[tid>>5] = l; }
    __syncthreads();
    if (tid == 0) {
        float M = -1e30f, L = 0.f;
        for (int i = 0; i < 8; i++) {
            float nm = fmaxf(M, redm[i]);
            L = L*__expf(M-nm) + reds[i]*__expf(redm[i]-nm);
            M = nm;
        }
        s_lse = M + logf(L);
    }
    __syncthreads();
    float lse = s_lse;
    float* row = out + (long)b*Vv;
    for (int v = tid*4; v < Vv; v += 1024) {
        float4 x = *(float4*)(row + v);
        x.x -= lse; x.y -= lse; x.z -= lse; x.w -= lse;
        *(float4*)(row + v) = x;
    }
}

// ---------------- launch ---------------------------------------------------
extern "C" void kernel_launch(void* const* d_in, const int* in_sizes, int n_in,
                              void* d_out, int out_size) {
    (void)in_sizes; (void)n_in; (void)out_size;
    const int*   ids    = (const int*)  d_in[0];
    const float* hidden = (const float*)d_in[1];
    const float* enc    = (const float*)d_in[2];
    const float* emb    = (const float*)d_in[3];
    const float* attnW  = (const float*)d_in[4];
    // d_in[5] = attn_b: per-batch constant in softmax argument — cancels.
    const float* W_ih   = (const float*)d_in[6];
    const float* W_hh   = (const float*)d_in[7];
    const float* b_ih   = (const float*)d_in[8];
    const float* b_hh   = (const float*)d_in[9];
    const float* outW   = (const float*)d_in[10];
    const float* outb   = (const float*)d_in[11];
    float* out = (float*)d_out;

    q_kernel<<<Bb, 256>>>(hidden, attnW);
    attn_partial<<<dim3(4, Bb), 512>>>(enc);
    attn_combine<<<Bb, 256>>>(ids, emb, out);
    gates_mma<<<dim3(24, 2, 4), 256>>>(hidden, W_ih, W_hh);
    gru_kernel<<<Bb, 256>>>(hidden, b_ih, b_hh, out);
    gemm_logits<<<NBLK, 256>>>(outW, outb, out);
    lse_kernel<<<Bb, 256>>>(out);
}

// round 10
// speedup vs baseline: 3.8468x; 1.1499x over previous
#include <cuda_runtime.h>
#include <cuda_bf16.h>
#include <cstdint>

#define Vv 32000
#define Hh 256
#define Ss 2048
#define Bb 128
#define BV (Bb*Vv)
#define NBLK 250           // gemm_logits blocks
#define NP   (NBLK*2)      // partial-softmax columns per row (2 n-halves/block)

// gemm_logits smem: 4 stages * (A 128x36 + B 16x136) words
#define AST 4608           // words per A stage (128*36)
#define BST 2176           // words per B stage (16*136)
#define SMEMB (4*(AST+BST)*4)

// ---------------- scratch (static __device__, no allocation) ----------------
__device__ float g_q[Bb*Hh];
__device__ float g_ctx[Bb*Hh];
__device__ float g_xcat[Bb*512];
__device__ float g_scores[Bb*Ss];
__device__ float g_partM[Bb*4];
__device__ float g_partL[Bb*4];
__device__ float g_ctxPart[Bb*4*Hh];
__device__ float g_gAp[4*Bb*768];   // split-K partials (no bias)
__device__ float g_gBp[4*Bb*768];
__device__ float g_pM[Bb*NP];       // per-block logit max partials
__device__ float g_pL[Bb*NP];       // per-block sumexp partials
__device__ __align__(16) uint32_t g_catT[Bb*512];   // [h_new, ctx] as tf32

__device__ __forceinline__ uint32_t tf32u(float x) {
    uint32_t u;
    asm("cvt.rna.tf32.f32 %0, %1;" : "=r"(u) : "f"(x));
    return u;
}

// ---------------- K0: q[b,h] = sum_k h[b,k] * We[k,h]  (We = attn_W[:,H:]) ----
__global__ void __launch_bounds__(256) q_kernel(const float* __restrict__ hidden,
                                                const float* __restrict__ attnW) {
    int b = blockIdx.x, h = threadIdx.x;
    __shared__ float hs[Hh];
    hs[h] = hidden[b*Hh + h];
    __syncthreads();
    float acc = 0.f;
#pragma unroll 8
    for (int k = 0; k < Hh; k++) acc += hs[k] * attnW[k*(2*Hh) + Hh + h];
    g_q[b*Hh + h] = acc;
}

// ---------------- K1a: flash-style partial attention over an s-chunk --------
__global__ void __launch_bounds__(512) attn_partial(const float* __restrict__ enc) {
    int b = blockIdx.y, sc = blockIdx.x;
    int tid = threadIdx.x;
    int w = tid >> 5, lane = tid & 31;
    __shared__ float qs[Hh];
    __shared__ float wm[16], wl[16];
    __shared__ float wctx[16][Hh];
    if (tid < Hh) qs[tid] = g_q[b*Hh + tid];
    __syncthreads();
    float qv[8];
#pragma unroll
    for (int k = 0; k < 8; k++) qv[k] = qs[lane*8 + k];

    const float* encb = enc + (long)b*Hh + (long)sc*512*(Bb*Hh) + lane*8;
    float m = -1e30f, l = 0.f;
    float c[8];
#pragma unroll
    for (int k = 0; k < 8; k++) c[k] = 0.f;

    for (int j0 = 0; j0 < 32; j0 += 4) {
        float e[4][8];
#pragma unroll
        for (int jj = 0; jj < 4; jj++) {
            const float* p = encb + (long)(w + 16*(j0+jj))*(Bb*Hh);
            float4 x0 = *(const float4*)p;
            float4 x1 = *(const float4*)(p+4);
            e[jj][0]=x0.x; e[jj][1]=x0.y; e[jj][2]=x0.z; e[jj][3]=x0.w;
            e[jj][4]=x1.x; e[jj][5]=x1.y; e[jj][6]=x1.z; e[jj][7]=x1.w;
        }
#pragma unroll
        for (int jj = 0; jj < 4; jj++) {
            float part = 0.f;
#pragma unroll
            for (int k = 0; k < 8; k++) part += e[jj][k]*qv[k];
#pragma unroll
            for (int o = 16; o; o >>= 1) part += __shfl_xor_sync(0xffffffffu, part, o);
            if (lane == 0) g_scores[b*Ss + sc*512 + w + 16*(j0+jj)] = part;
            float nm  = fmaxf(m, part);
            float scl = __expf(m - nm);
            float p_  = __expf(part - nm);
            l = l*scl + p_;
#pragma unroll
            for (int k = 0; k < 8; k++) c[k] = c[k]*scl + p_*e[jj][k];
            m = nm;
        }
    }
    if (lane == 0) { wm[w] = m; wl[w] = l; }
#pragma unroll
    for (int k = 0; k < 8; k++) wctx[w][lane*8+k] = c[k];
    __syncthreads();
    if (tid < Hh) {
        float gm = -1e30f;
        for (int i = 0; i < 16; i++) gm = fmaxf(gm, wm[i]);
        float L = 0.f, cv = 0.f;
        for (int i = 0; i < 16; i++) {
            float f = __expf(wm[i] - gm);
            L  += wl[i]*f;
            cv += wctx[i][tid]*f;
        }
        g_ctxPart[(b*4+sc)*Hh + tid] = cv;
        if (tid == 0) { g_partM[b*4+sc] = gm; g_partL[b*4+sc] = L; }
    }
}

// ---------------- K1b: combine partials, write attn_weights + context + xcat
__global__ void __launch_bounds__(256) attn_combine(const int* __restrict__ ids,
                                                    const float* __restrict__ emb,
                                                    float* __restrict__ out) {
    int b = blockIdx.x, tid = threadIdx.x;
    float m0 = g_partM[b*4+0], m1 = g_partM[b*4+1], m2 = g_partM[b*4+2], m3 = g_partM[b*4+3];
    float gm = fmaxf(fmaxf(m0,m1), fmaxf(m2,m3));
    float f0 = __expf(m0-gm), f1 = __expf(m1-gm), f2 = __expf(m2-gm), f3 = __expf(m3-gm);
    float L = g_partL[b*4+0]*f0 + g_partL[b*4+1]*f1 + g_partL[b*4+2]*f2 + g_partL[b*4+3]*f3;
    float cv = g_ctxPart[(b*4+0)*Hh+tid]*f0 + g_ctxPart[(b*4+1)*Hh+tid]*f1
             + g_ctxPart[(b*4+2)*Hh+tid]*f2 + g_ctxPart[(b*4+3)*Hh+tid]*f3;
    float ctx = cv / L;
    g_ctx[b*Hh + tid] = ctx;
    g_xcat[b*512 + tid]       = emb[(long)ids[b]*Hh + tid];
    g_xcat[b*512 + 256 + tid] = ctx;
    float invL = 1.f / L;
    for (int s = tid; s < Ss; s += 256)
        out[BV + Bb*Hh + b*Ss + s] = __expf(g_scores[b*Ss+s] - gm) * invL;
}

// ---------------- K2: gates TF32 GEMM, split-K x4 ---------------------------
__global__ void __launch_bounds__(256) gates_mma(const float* __restrict__ hidden,
        const float* __restrict__ W_ih, const float* __restrict__ W_hh) {
    __shared__ uint32_t As[2][128*36];
    __shared__ uint32_t Bs[2][32*36];

    int phase = blockIdx.y, z = blockIdx.z;
    const float* SRC  = phase ? hidden : g_xcat;
    const float* WPTR = phase ? W_hh   : W_ih;
    float*       dst  = (phase ? g_gBp : g_gAp) + z*(Bb*768);
    int LD = phase ? 256 : 512;
    int KT = phase ? 2   : 4;
    int kbase = z * KT * 32;

    int n0  = blockIdx.x * 32;
    int tid = threadIdx.x;
    int w = tid >> 5, lane = tid & 31;
    int wm = (w >> 1) * 32, wn = (w & 1) * 16;
    int g = lane >> 2, i4 = lane & 3;

    int arow = tid >> 3, acol = (tid & 7) * 4;
    int brow = tid >> 3, bcol = (tid & 7) * 4;

    float accA[2][2][4];
#pragma unroll
    for (int mt = 0; mt < 2; mt++)
#pragma unroll
        for (int nt = 0; nt < 2; nt++)
#pragma unroll
            for (int c = 0; c < 4; c++) accA[mt][nt][c] = 0.f;

    float4 ra[4]; float4 rb;
#pragma unroll
    for (int it = 0; it < 4; it++)
        ra[it] = *(const float4*)(SRC + (long)(arow + it*32)*LD + kbase + acol);
    rb = *(const float4*)(WPTR + (long)(n0 + brow)*LD + kbase + bcol);
#pragma unroll
    for (int it = 0; it < 4; it++) {
        int r = arow + it*32;
        As[0][r*36+acol+0] = tf32u(ra[it].x); As[0][r*36+acol+1] = tf32u(ra[it].y);
        As[0][r*36+acol+2] = tf32u(ra[it].z); As[0][r*36+acol+3] = tf32u(ra[it].w);
    }
    Bs[0][brow*36+bcol+0] = tf32u(rb.x); Bs[0][brow*36+bcol+1] = tf32u(rb.y);
    Bs[0][brow*36+bcol+2] = tf32u(rb.z); Bs[0][brow*36+bcol+3] = tf32u(rb.w);
    __syncthreads();

    for (int kt = 0; kt < KT; kt++) {
        int cur = kt & 1;
        if (kt + 1 < KT) {
            int k0 = kbase + (kt + 1) * 32;
#pragma unroll
            for (int it = 0; it < 4; it++)
                ra[it] = *(const float4*)(SRC + (long)(arow + it*32)*LD + k0 + acol);
            rb = *(const float4*)(WPTR + (long)(n0 + brow)*LD + k0 + bcol);
        }
#pragma unroll
        for (int ks = 0; ks < 4; ks++) {
            uint32_t a[2][4];
#pragma unroll
            for (int mt = 0; mt < 2; mt++) {
                int m = wm + mt*16;
                a[mt][0] = As[cur][(m+g   )*36 + ks*8 + i4    ];
                a[mt][1] = As[cur][(m+g+8 )*36 + ks*8 + i4    ];
                a[mt][2] = As[cur][(m+g   )*36 + ks*8 + i4 + 4];
                a[mt][3] = As[cur][(m+g+8 )*36 + ks*8 + i4 + 4];
            }
#pragma unroll
            for (int nt = 0; nt < 2; nt++) {
                uint32_t b0 = Bs[cur][(wn+nt*8+g)*36 + ks*8 + i4    ];
                uint32_t b1 = Bs[cur][(wn+nt*8+g)*36 + ks*8 + i4 + 4];
#pragma unroll
                for (int mt = 0; mt < 2; mt++) {
                    asm volatile(
                        "mma.sync.aligned.m16n8k8.row.col.f32.tf32.tf32.f32 "
                        "{%0,%1,%2,%3}, {%4,%5,%6,%7}, {%8,%9}, {%0,%1,%2,%3};\n"
                        : "+f"(accA[mt][nt][0]), "+f"(accA[mt][nt][1]),
                          "+f"(accA[mt][nt][2]), "+f"(accA[mt][nt][3])
                        : "r"(a[mt][0]), "r"(a[mt][1]), "r"(a[mt][2]), "r"(a[mt][3]),
                          "r"(b0), "r"(b1));
                }
            }
        }
        if (kt + 1 < KT) {
            int nxt = 1 - cur;
#pragma unroll
            for (int it = 0; it < 4; it++) {
                int r = arow + it*32;
                As[nxt][r*36+acol+0] = tf32u(ra[it].x); As[nxt][r*36+acol+1] = tf32u(ra[it].y);
                As[nxt][r*36+acol+2] = tf32u(ra[it].z); As[nxt][r*36+acol+3] = tf32u(ra[it].w);
            }
            Bs[nxt][brow*36+bcol+0] = tf32u(rb.x); Bs[nxt][brow*36+bcol+1] = tf32u(rb.y);
            Bs[nxt][brow*36+bcol+2] = tf32u(rb.z); Bs[nxt][brow*36+bcol+3] = tf32u(rb.w);
        }
        __syncthreads();
    }

#pragma unroll
    for (int mt = 0; mt < 2; mt++) {
        int m = wm + mt*16 + g;
#pragma unroll
        for (int nt = 0; nt < 2; nt++) {
            int n = n0 + wn + nt*8 + 2*i4;
            dst[(m  )*768 + n  ] = accA[mt][nt][0];
            dst[(m  )*768 + n+1] = accA[mt][nt][1];
            dst[(m+8)*768 + n  ] = accA[mt][nt][2];
            dst[(m+8)*768 + n+1] = accA[mt][nt][3];
        }
    }
}

// ---------------- K3: GRU combine (reduces split-K partials), emits tf32 cat
__global__ void __launch_bounds__(256) gru_kernel(const float* __restrict__ hidden,
        const float* __restrict__ b_ih, const float* __restrict__ b_hh,
        float* __restrict__ out) {
    int b = blockIdx.x, t = threadIdx.x;
#define SUM4(P, IDX) (P[IDX] + P[(Bb*768)+(IDX)] + P[2*(Bb*768)+(IDX)] + P[3*(Bb*768)+(IDX)])
    int i0 = b*768 + t, i1 = i0 + 256, i2 = i0 + 512;
    float Ar = SUM4(g_gAp, i0) + b_ih[t];
    float Az = SUM4(g_gAp, i1) + b_ih[256+t];
    float An = SUM4(g_gAp, i2) + b_ih[512+t];
    float Br = SUM4(g_gBp, i0) + b_hh[t];
    float Bz = SUM4(g_gBp, i1) + b_hh[256+t];
    float Bn = SUM4(g_gBp, i2) + b_hh[512+t];
#undef SUM4
    float r  = 1.f/(1.f + __expf(-(Ar+Br)));
    float z  = 1.f/(1.f + __expf(-(Az+Bz)));
    float n  = tanhf(An + r*Bn);
    float h  = hidden[b*Hh + t];
    float hn = (1.f - z)*n + z*h;
    out[BV + b*Hh + t] = hn;
    float ctx = g_ctx[b*Hh + t];
    g_catT[b*512 + t]       = tf32u(hn);
    g_catT[b*512 + 256 + t] = tf32u(ctx);
}

// ---------------- K4: logits TF32 GEMM, cp.async 4-stage + fused lse partials
// Block: 128(v) x 128(m); 8 warps = 4(m) x 2(n); per-warp 32m x 64v.
__global__ void __launch_bounds__(256) gemm_logits(const float* __restrict__ outW,
        const float* __restrict__ outb, float* __restrict__ out) {
    extern __shared__ uint32_t sm[];
    uint32_t* Asm = sm;              // 4 stages x AST
    uint32_t* Bsm = sm + 4*AST;      // 4 stages x BST

    int blk = blockIdx.x;
    int v0  = blk * 128;
    int tid = threadIdx.x;
    int w = tid >> 5, lane = tid & 31;
    int g = lane >> 2, i4 = lane & 3;
    int wmA = (w >> 1) * 32;         // warp m base
    int wnB = (w & 1) * 64;          // warp n base

    int mA = tid >> 1, hf = tid & 1;       // A cp.async: row, k-half
    int kk = tid >> 4, vv = (tid & 15)*8;  // B cp.async: k row, v offset

    float acc[2][8][4];
#pragma unroll
    for (int mt = 0; mt < 2; mt++)
#pragma unroll
        for (int nt = 0; nt < 8; nt++)
#pragma unroll
            for (int c = 0; c < 4; c++) acc[mt][nt][c] = 0.f;

    uint32_t aDst = (uint32_t)__cvta_generic_to_shared(Asm) + (mA*36 + hf*8)*4u;
    uint32_t bDst = (uint32_t)__cvta_generic_to_shared(Bsm) + (kk*136 + vv)*4u;
    const uint32_t* aSrc = g_catT + mA*512 + hf*8;

#define ISSUE(ST, KT) do {                                                         \
    uint32_t ad = aDst + (ST)*AST*4u;                                              \
    const uint32_t* as_ = aSrc + (KT)*16;                                          \
    asm volatile("cp.async.cg.shared.global [%0], [%1], 16;\n" :: "r"(ad), "l"(as_)); \
    asm volatile("cp.async.cg.shared.global [%0], [%1], 16;\n" :: "r"(ad+16), "l"(as_+4)); \
    uint32_t bd = bDst + (ST)*BST*4u;                                              \
    const float* bs_ = outW + (long)((KT)*16 + kk)*Vv + v0 + vv;                   \
    asm volatile("cp.async.cg.shared.global [%0], [%1], 16;\n" :: "r"(bd), "l"(bs_)); \
    asm volatile("cp.async.cg.shared.global [%0], [%1], 16;\n" :: "r"(bd+16), "l"(bs_+4)); \
    asm volatile("cp.async.commit_group;\n");                                      \
} while (0)

    ISSUE(0, 0); ISSUE(1, 1); ISSUE(2, 2);

    for (int kt = 0; kt < 32; kt++) {
        int st = kt & 3;
        asm volatile("cp.async.wait_group 2;\n" ::: "memory");
        __syncthreads();
        if (kt + 3 < 32) ISSUE((kt + 3) & 3, kt + 3);   // writes stage (kt-1)&3: consumed
        const uint32_t* A_ = Asm + st*AST;
        const uint32_t* B_ = Bsm + st*BST;
#pragma unroll
        for (int ks = 0; ks < 2; ks++) {
            uint32_t a[2][4];
#pragma unroll
            for (int mt = 0; mt < 2; mt++) {
                int m = wmA + mt*16;
                a[mt][0] = A_[(m+g   )*36 + ks*8 + i4    ];
                a[mt][1] = A_[(m+g+8 )*36 + ks*8 + i4    ];
                a[mt][2] = A_[(m+g   )*36 + ks*8 + i4 + 4];
                a[mt][3] = A_[(m+g+8 )*36 + ks*8 + i4 + 4];
            }
#pragma unroll
            for (int nt = 0; nt < 8; nt++) {
                uint32_t b0 = B_[(ks*8 + i4    )*136 + wnB + nt*8 + g];
                uint32_t b1 = B_[(ks*8 + i4 + 4)*136 + wnB + nt*8 + g];
#pragma unroll
                for (int mt = 0; mt < 2; mt++) {
                    asm volatile(
                        "mma.sync.aligned.m16n8k8.row.col.f32.tf32.tf32.f32 "
                        "{%0,%1,%2,%3}, {%4,%5,%6,%7}, {%8,%9}, {%0,%1,%2,%3};\n"
                        : "+f"(acc[mt][nt][0]), "+f"(acc[mt][nt][1]),
                          "+f"(acc[mt][nt][2]), "+f"(acc[mt][nt][3])
                        : "r"(a[mt][0]), "r"(a[mt][1]), "r"(a[mt][2]), "r"(a[mt][3]),
                          "r"(b0), "r"(b1));
                }
            }
        }
        __syncthreads();
    }
#undef ISSUE

    // epilogue: bias, store logits, fused partial log-softmax (per 64-col half)
    float ob0s[8], ob1s[8];
#pragma unroll
    for (int nt = 0; nt < 8; nt++) {
        int v = v0 + wnB + nt*8 + 2*i4;
        ob0s[nt] = outb[v]; ob1s[nt] = outb[v+1];
    }
    float mx[2][2] = {{-1e30f,-1e30f},{-1e30f,-1e30f}};
#pragma unroll
    for (int mt = 0; mt < 2; mt++) {
        long ro = (long)(wmA + mt*16 + g)*Vv;
#pragma unroll
        for (int nt = 0; nt < 8; nt++) {
            int v = v0 + wnB + nt*8 + 2*i4;
            float r0 = acc[mt][nt][0]+ob0s[nt], r1 = acc[mt][nt][1]+ob1s[nt];
            float r2 = acc[mt][nt][2]+ob0s[nt], r3 = acc[mt][nt][3]+ob1s[nt];
            *(float2*)(out + ro + v)          = make_float2(r0, r1);
            *(float2*)(out + ro + 8L*Vv + v)  = make_float2(r2, r3);
            mx[mt][0] = fmaxf(mx[mt][0], fmaxf(r0, r1));
            mx[mt][1] = fmaxf(mx[mt][1], fmaxf(r2, r3));
        }
    }
    float ss[2][2] = {{0.f,0.f},{0.f,0.f}};
#pragma unroll
    for (int mt = 0; mt < 2; mt++)
#pragma unroll
        for (int nt = 0; nt < 8; nt++) {
            ss[mt][0] += __expf(acc[mt][nt][0]+ob0s[nt]-mx[mt][0])
                       + __expf(acc[mt][nt][1]+ob1s[nt]-mx[mt][0]);
            ss[mt][1] += __expf(acc[mt][nt][2]+ob0s[nt]-mx[mt][1])
                       + __expf(acc[mt][nt][3]+ob1s[nt]-mx[mt][1]);
        }
#pragma unroll
    for (int o = 1; o <= 2; o <<= 1) {
#pragma unroll
        for (int mt = 0; mt < 2; mt++)
#pragma unroll
            for (int hh = 0; hh < 2; hh++) {
                float om = __shfl_xor_sync(0xffffffffu, mx[mt][hh], o);
                float os = __shfl_xor_sync(0xffffffffu, ss[mt][hh], o);
                float nm = fmaxf(mx[mt][hh], om);
                ss[mt][hh] = ss[mt][hh]*__expf(mx[mt][hh]-nm) + os*__expf(om-nm);
                mx[mt][hh] = nm;
            }
    }
    if (i4 == 0) {
        int pc = blk*2 + (w & 1);
#pragma unroll
        for (int mt = 0; mt < 2; mt++)
#pragma unroll
            for (int hh = 0; hh < 2; hh++) {
                int row = wmA + mt*16 + g + hh*8;
                g_pM[row*NP + pc] = mx[mt][hh];
                g_pL[row*NP + pc] = ss[mt][hh];
            }
    }
}

// ---------------- K5: merge partials + subtract lse (single pass over V) ----
__global__ void __launch_bounds__(256) lse_kernel(float* __restrict__ out) {
    __shared__ float redm[8], reds[8];
    __shared__ float s_lse;
    int b = blockIdx.x, tid = threadIdx.x;
    float m = -1e30f, l = 0.f;
    for (int p = tid; p < NP; p += 256) {
        float pm = g_pM[b*NP + p], pl = g_pL[b*NP + p];
        float nm = fmaxf(m, pm);
        l = l*__expf(m-nm) + pl*__expf(pm-nm);
        m = nm;
    }
#pragma unroll
    for (int o = 16; o; o >>= 1) {
        float om = __shfl_xor_sync(0xffffffffu, m, o);
        float ol = __shfl_xor_sync(0xffffffffu, l, o);
        float nm = fmaxf(m, om);
        l = l*__expf(m-nm) + ol*__expf(om-nm);
        m = nm;
    }
    if ((tid & 31) == 0) { redm[tid>>5] = m; reds[tid>>5] = l; }
    __syncthreads();
    if (tid == 0) {
        float M = -1e30f, L = 0.f;
        for (int i = 0; i < 8; i++) {
            float nm = fmaxf(M, redm[i]);
            L = L*__expf(M-nm) + reds[i]*__expf(redm[i]-nm);
            M = nm;
        }
        s_lse = M + logf(L);
    }
    __syncthreads();
    float lse = s_lse;
    float* row = out + (long)b*Vv;
    for (int v = tid*4; v < Vv; v += 1024) {
        float4 x = *(float4*)(row + v);
        x.x -= lse; x.y -= lse; x.z -= lse; x.w -= lse;
        *(float4*)(row + v) = x;
    }
}

// ---------------- launch ---------------------------------------------------
extern "C" void kernel_launch(void* const* d_in, const int* in_sizes, int n_in,
                              void* d_out, int out_size) {
    (void)in_sizes; (void)n_in; (void)out_size;
    const int*   ids    = (const int*)  d_in[0];
    const float* hidden = (const float*)d_in[1];
    const float* enc    = (const float*)d_in[2];
    const float* emb    = (const float*)d_in[3];
    const float* attnW  = (const float*)d_in[4];
    // d_in[5] = attn_b: per-batch constant in softmax argument — cancels.
    const float* W_ih   = (const float*)d_in[6];
    const float* W_hh   = (const float*)d_in[7];
    const float* b_ih   = (const float*)d_in[8];
    const float* b_hh   = (const float*)d_in[9];
    const float* outW   = (const float*)d_in[10];
    const float* outb   = (const float*)d_in[11];
    float* out = (float*)d_out;

    static bool attr_done = false;
    if (!attr_done) {
        cudaFuncSetAttribute(gemm_logits,
                             cudaFuncAttributeMaxDynamicSharedMemorySize, SMEMB);
        attr_done = true;
    }

    q_kernel<<<Bb, 256>>>(hidden, attnW);
    attn_partial<<<dim3(4, Bb), 512>>>(enc);
    attn_combine<<<Bb, 256>>>(ids, emb, out);
    gates_mma<<<dim3(24, 2, 4), 256>>>(hidden, W_ih, W_hh);
    gru_kernel<<<Bb, 256>>>(hidden, b_ih, b_hh, out);
    gemm_logits<<<NBLK, 256, SMEMB>>>(outW, outb, out);
    lse_kernel<<<Bb, 256>>>(out);
}

// round 12
// speedup vs baseline: 4.1320x; 1.0741x over previous
#include <cuda_runtime.h>
#include <cuda_bf16.h>
#include <cstdint>

#define Vv 32000
#define Hh 256
#define Ss 2048
#define Bb 128
#define BV (Bb*Vv)
#define NBLK 250           // gemm_logits blocks
#define NP   (NBLK*2)      // partial-softmax columns per row (2 n-halves/block)

// gemm_logits smem: 3 stages * (A 128x36 + B 16x136) words
#define AST 4608           // words per A stage (128*36)
#define BST 2176           // words per B stage (16*136)
#define NSTG 3
#define SMEMB (NSTG*(AST+BST)*4)

// ---------------- scratch (static __device__, no allocation) ----------------
__device__ float g_q[Bb*Hh];
__device__ float g_ctx[Bb*Hh];
__device__ float g_xcat[Bb*512];
__device__ float g_scores[Bb*Ss];
__device__ float g_partM[Bb*4];
__device__ float g_partL[Bb*4];
__device__ float g_ctxPart[Bb*4*Hh];
__device__ float g_gAp[4*Bb*768];   // split-K partials (no bias)
__device__ float g_gBp[4*Bb*768];
__device__ float g_pM[Bb*NP];       // per-block logit max partials
__device__ float g_pL[Bb*NP];       // per-block sumexp partials
__device__ float g_lse[Bb];
__device__ __align__(16) uint32_t g_catT[Bb*512];   // [h_new, ctx] as tf32

__device__ __forceinline__ uint32_t tf32u(float x) {
    uint32_t u;
    asm("cvt.rna.tf32.f32 %0, %1;" : "=r"(u) : "f"(x));
    return u;
}

__device__ __forceinline__ void l2_prefetch(const void* p) {
    asm volatile("prefetch.global.L2 [%0];" :: "l"(p));
}

// ---------------- K0: q[b,h] = sum_k h[b,k] * We[k,h]  (We = attn_W[:,H:]) ----
__global__ void __launch_bounds__(256) q_kernel(const float* __restrict__ hidden,
                                                const float* __restrict__ attnW) {
    int b = blockIdx.x, h = threadIdx.x;
    __shared__ float hs[Hh];
    hs[h] = hidden[b*Hh + h];
    __syncthreads();
    float acc = 0.f;
#pragma unroll 8
    for (int k = 0; k < Hh; k++) acc += hs[k] * attnW[k*(2*Hh) + Hh + h];
    g_q[b*Hh + h] = acc;
}

// ---------------- K1a: flash attention partials + L2 prefetch of weights ----
// sc in [0,4): attention over 512-s chunk (enc streamed with .cs)
// sc in [4,6): prefetch outW into L2
// sc == 6   : prefetch W_ih, W_hh into L2
__global__ void __launch_bounds__(512) attn_partial(const float* __restrict__ enc,
        const float* __restrict__ outW, const float* __restrict__ W_ih,
        const float* __restrict__ W_hh) {
    int b = blockIdx.y, sc = blockIdx.x;
    int tid = threadIdx.x;

    if (sc >= 4) {
        // prefetch.global.L2: one line (128B = 32 floats) per iteration
        if (sc < 6) {
            int pid = (sc - 4)*Bb + b;                       // 0..255 slices
            const float* src = outW + (long)pid*64000;       // 16.384M floats / 256
            for (int t = tid; t < 2000; t += 512)
                l2_prefetch(src + t*32);
        } else {
            const float* s1 = W_ih + (long)b*3072;           // 768*512 floats /128
            for (int t = tid; t < 96; t += 512)
                l2_prefetch(s1 + t*32);
            const float* s2 = W_hh + (long)b*1536;
            for (int t = tid; t < 48; t += 512)
                l2_prefetch(s2 + t*32);
        }
        return;
    }

    int w = tid >> 5, lane = tid & 31;
    __shared__ float qs[Hh];
    __shared__ float wm[16], wl[16];
    __shared__ float wctx[16][Hh];
    if (tid < Hh) qs[tid] = g_q[b*Hh + tid];
    __syncthreads();
    float qv[8];
#pragma unroll
    for (int k = 0; k < 8; k++) qv[k] = qs[lane*8 + k];

    const float* encb = enc + (long)b*Hh + (long)sc*512*(Bb*Hh) + lane*8;
    float m = -1e30f, l = 0.f;
    float c[8];
#pragma unroll
    for (int k = 0; k < 8; k++) c[k] = 0.f;

    for (int j0 = 0; j0 < 32; j0 += 4) {
        float e[4][8];
#pragma unroll
        for (int jj = 0; jj < 4; jj++) {
            const float* p = encb + (long)(w + 16*(j0+jj))*(Bb*Hh);
            float4 x0 = __ldcs((const float4*)p);       // streaming: evict-first
            float4 x1 = __ldcs((const float4*)(p+4));
            e[jj][0]=x0.x; e[jj][1]=x0.y; e[jj][2]=x0.z; e[jj][3]=x0.w;
            e[jj][4]=x1.x; e[jj][5]=x1.y; e[jj][6]=x1.z; e[jj][7]=x1.w;
        }
#pragma unroll
        for (int jj = 0; jj < 4; jj++) {
            float part = 0.f;
#pragma unroll
            for (int k = 0; k < 8; k++) part += e[jj][k]*qv[k];
#pragma unroll
            for (int o = 16; o; o >>= 1) part += __shfl_xor_sync(0xffffffffu, part, o);
            if (lane == 0) g_scores[b*Ss + sc*512 + w + 16*(j0+jj)] = part;
            float nm  = fmaxf(m, part);
            float scl = __expf(m - nm);
            float p_  = __expf(part - nm);
            l = l*scl + p_;
#pragma unroll
            for (int k = 0; k < 8; k++) c[k] = c[k]*scl + p_*e[jj][k];
            m = nm;
        }
    }
    if (lane == 0) { wm[w] = m; wl[w] = l; }
#pragma unroll
    for (int k = 0; k < 8; k++) wctx[w][lane*8+k] = c[k];
    __syncthreads();
    if (tid < Hh) {
        float gm = -1e30f;
        for (int i = 0; i < 16; i++) gm = fmaxf(gm, wm[i]);
        float L = 0.f, cv = 0.f;
        for (int i = 0; i < 16; i++) {
            float f = __expf(wm[i] - gm);
            L  += wl[i]*f;
            cv += wctx[i][tid]*f;
        }
        g_ctxPart[(b*4+sc)*Hh + tid] = cv;
        if (tid == 0) { g_partM[b*4+sc] = gm; g_partL[b*4+sc] = L; }
    }
}

// ---------------- K1b: combine partials, write attn_weights + context + xcat
__global__ void __launch_bounds__(256) attn_combine(const int* __restrict__ ids,
                                                    const float* __restrict__ emb,
                                                    float* __restrict__ out) {
    int b = blockIdx.x, tid = threadIdx.x;
    float m0 = g_partM[b*4+0], m1 = g_partM[b*4+1], m2 = g_partM[b*4+2], m3 = g_partM[b*4+3];
    float gm = fmaxf(fmaxf(m0,m1), fmaxf(m2,m3));
    float f0 = __expf(m0-gm), f1 = __expf(m1-gm), f2 = __expf(m2-gm), f3 = __expf(m3-gm);
    float L = g_partL[b*4+0]*f0 + g_partL[b*4+1]*f1 + g_partL[b*4+2]*f2 + g_partL[b*4+3]*f3;
    float cv = g_ctxPart[(b*4+0)*Hh+tid]*f0 + g_ctxPart[(b*4+1)*Hh+tid]*f1
             + g_ctxPart[(b*4+2)*Hh+tid]*f2 + g_ctxPart[(b*4+3)*Hh+tid]*f3;
    float ctx = cv / L;
    g_ctx[b*Hh + tid] = ctx;
    g_xcat[b*512 + tid]       = emb[(long)ids[b]*Hh + tid];
    g_xcat[b*512 + 256 + tid] = ctx;
    float invL = 1.f / L;
    for (int s = tid; s < Ss; s += 256)
        out[BV + Bb*Hh + b*Ss + s] = __expf(g_scores[b*Ss+s] - gm) * invL;
}

// ---------------- K2: gates TF32 GEMM, split-K x4 ---------------------------
__global__ void __launch_bounds__(256) gates_mma(const float* __restrict__ hidden,
        const float* __restrict__ W_ih, const float* __restrict__ W_hh) {
    __shared__ uint32_t As[2][128*36];
    __shared__ uint32_t Bs[2][32*36];

    int phase = blockIdx.y, z = blockIdx.z;
    const float* SRC  = phase ? hidden : g_xcat;
    const float* WPTR = phase ? W_hh   : W_ih;
    float*       dst  = (phase ? g_gBp : g_gAp) + z*(Bb*768);
    int LD = phase ? 256 : 512;
    int KT = phase ? 2   : 4;
    int kbase = z * KT * 32;

    int n0  = blockIdx.x * 32;
    int tid = threadIdx.x;
    int w = tid >> 5, lane = tid & 31;
    int wm = (w >> 1) * 32, wn = (w & 1) * 16;
    int g = lane >> 2, i4 = lane & 3;

    int arow = tid >> 3, acol = (tid & 7) * 4;
    int brow = tid >> 3, bcol = (tid & 7) * 4;

    float accA[2][2][4];
#pragma unroll
    for (int mt = 0; mt < 2; mt++)
#pragma unroll
        for (int nt = 0; nt < 2; nt++)
#pragma unroll
            for (int c = 0; c < 4; c++) accA[mt][nt][c] = 0.f;

    float4 ra[4]; float4 rb;
#pragma unroll
    for (int it = 0; it < 4; it++)
        ra[it] = *(const float4*)(SRC + (long)(arow + it*32)*LD + kbase + acol);
    rb = *(const float4*)(WPTR + (long)(n0 + brow)*LD + kbase + bcol);
#pragma unroll
    for (int it = 0; it < 4; it++) {
        int r = arow + it*32;
        As[0][r*36+acol+0] = tf32u(ra[it].x); As[0][r*36+acol+1] = tf32u(ra[it].y);
        As[0][r*36+acol+2] = tf32u(ra[it].z); As[0][r*36+acol+3] = tf32u(ra[it].w);
    }
    Bs[0][brow*36+bcol+0] = tf32u(rb.x); Bs[0][brow*36+bcol+1] = tf32u(rb.y);
    Bs[0][brow*36+bcol+2] = tf32u(rb.z); Bs[0][brow*36+bcol+3] = tf32u(rb.w);
    __syncthreads();

    for (int kt = 0; kt < KT; kt++) {
        int cur = kt & 1;
        if (kt + 1 < KT) {
            int k0 = kbase + (kt + 1) * 32;
#pragma unroll
            for (int it = 0; it < 4; it++)
                ra[it] = *(const float4*)(SRC + (long)(arow + it*32)*LD + k0 + acol);
            rb = *(const float4*)(WPTR + (long)(n0 + brow)*LD + k0 + bcol);
        }
#pragma unroll
        for (int ks = 0; ks < 4; ks++) {
            uint32_t a[2][4];
#pragma unroll
            for (int mt = 0; mt < 2; mt++) {
                int m = wm + mt*16;
                a[mt][0] = As[cur][(m+g   )*36 + ks*8 + i4    ];
                a[mt][1] = As[cur][(m+g+8 )*36 + ks*8 + i4    ];
                a[mt][2] = As[cur][(m+g   )*36 + ks*8 + i4 + 4];
                a[mt][3] = As[cur][(m+g+8 )*36 + ks*8 + i4 + 4];
            }
#pragma unroll
            for (int nt = 0; nt < 2; nt++) {
                uint32_t b0 = Bs[cur][(wn+nt*8+g)*36 + ks*8 + i4    ];
                uint32_t b1 = Bs[cur][(wn+nt*8+g)*36 + ks*8 + i4 + 4];
#pragma unroll
                for (int mt = 0; mt < 2; mt++) {
                    asm volatile(
                        "mma.sync.aligned.m16n8k8.row.col.f32.tf32.tf32.f32 "
                        "{%0,%1,%2,%3}, {%4,%5,%6,%7}, {%8,%9}, {%0,%1,%2,%3};\n"
                        : "+f"(accA[mt][nt][0]), "+f"(accA[mt][nt][1]),
                          "+f"(accA[mt][nt][2]), "+f"(accA[mt][nt][3])
                        : "r"(a[mt][0]), "r"(a[mt][1]), "r"(a[mt][2]), "r"(a[mt][3]),
                          "r"(b0), "r"(b1));
                }
            }
        }
        if (kt + 1 < KT) {
            int nxt = 1 - cur;
#pragma unroll
            for (int it = 0; it < 4; it++) {
                int r = arow + it*32;
                As[nxt][r*36+acol+0] = tf32u(ra[it].x); As[nxt][r*36+acol+1] = tf32u(ra[it].y);
                As[nxt][r*36+acol+2] = tf32u(ra[it].z); As[nxt][r*36+acol+3] = tf32u(ra[it].w);
            }
            Bs[nxt][brow*36+bcol+0] = tf32u(rb.x); Bs[nxt][brow*36+bcol+1] = tf32u(rb.y);
            Bs[nxt][brow*36+bcol+2] = tf32u(rb.z); Bs[nxt][brow*36+bcol+3] = tf32u(rb.w);
        }
        __syncthreads();
    }

#pragma unroll
    for (int mt = 0; mt < 2; mt++) {
        int m = wm + mt*16 + g;
#pragma unroll
        for (int nt = 0; nt < 2; nt++) {
            int n = n0 + wn + nt*8 + 2*i4;
            dst[(m  )*768 + n  ] = accA[mt][nt][0];
            dst[(m  )*768 + n+1] = accA[mt][nt][1];
            dst[(m+8)*768 + n  ] = accA[mt][nt][2];
            dst[(m+8)*768 + n+1] = accA[mt][nt][3];
        }
    }
}

// ---------------- K3: GRU combine (reduces split-K partials), emits tf32 cat
__global__ void __launch_bounds__(256) gru_kernel(const float* __restrict__ hidden,
        const float* __restrict__ b_ih, const float* __restrict__ b_hh,
        float* __restrict__ out) {
    int b = blockIdx.x, t = threadIdx.x;
#define SUM4(P, IDX) (P[IDX] + P[(Bb*768)+(IDX)] + P[2*(Bb*768)+(IDX)] + P[3*(Bb*768)+(IDX)])
    int i0 = b*768 + t, i1 = i0 + 256, i2 = i0 + 512;
    float Ar = SUM4(g_gAp, i0) + b_ih[t];
    float Az = SUM4(g_gAp, i1) + b_ih[256+t];
    float An = SUM4(g_gAp, i2) + b_ih[512+t];
    float Br = SUM4(g_gBp, i0) + b_hh[t];
    float Bz = SUM4(g_gBp, i1) + b_hh[256+t];
    float Bn = SUM4(g_gBp, i2) + b_hh[512+t];
#undef SUM4
    float r  = 1.f/(1.f + __expf(-(Ar+Br)));
    float z  = 1.f/(1.f + __expf(-(Az+Bz)));
    float n  = tanhf(An + r*Bn);
    float h  = hidden[b*Hh + t];
    float hn = (1.f - z)*n + z*h;
    out[BV + b*Hh + t] = hn;
    float ctx = g_ctx[b*Hh + t];
    g_catT[b*512 + t]       = tf32u(hn);
    g_catT[b*512 + 256 + t] = tf32u(ctx);
}

// ---------------- K4: logits TF32 GEMM, cp.async 3-stage, occ 2 -------------
// Block: 128(v) x 128(m); 8 warps = 4(m) x 2(n); per-warp 32m x 64v.
__global__ void __launch_bounds__(256, 2) gemm_logits(const float* __restrict__ outW,
        const float* __restrict__ outb, float* __restrict__ out) {
    extern __shared__ uint32_t sm[];
    uint32_t* Asm = sm;               // NSTG stages x AST
    uint32_t* Bsm = sm + NSTG*AST;    // NSTG stages x BST

    int blk = blockIdx.x;
    int v0  = blk * 128;
    int tid = threadIdx.x;
    int w = tid >> 5, lane = tid & 31;
    int g = lane >> 2, i4 = lane & 3;
    int wmA = (w >> 1) * 32;
    int wnB = (w & 1) * 64;

    int mA = tid >> 1, hf = tid & 1;
    int kk = tid >> 4, vv = (tid & 15)*8;

    float acc[2][8][4];
#pragma unroll
    for (int mt = 0; mt < 2; mt++)
#pragma unroll
        for (int nt = 0; nt < 8; nt++)
#pragma unroll
            for (int c = 0; c < 4; c++) acc[mt][nt][c] = 0.f;

    uint32_t aDst = (uint32_t)__cvta_generic_to_shared(Asm) + (mA*36 + hf*8)*4u;
    uint32_t bDst = (uint32_t)__cvta_generic_to_shared(Bsm) + (kk*136 + vv)*4u;
    const uint32_t* aSrc = g_catT + mA*512 + hf*8;

#define ISSUE(ST, KT) do {                                                         \
    uint32_t ad = aDst + (ST)*AST*4u;                                              \
    const uint32_t* as_ = aSrc + (KT)*16;                                          \
    asm volatile("cp.async.cg.shared.global [%0], [%1], 16;\n" :: "r"(ad), "l"(as_)); \
    asm volatile("cp.async.cg.shared.global [%0], [%1], 16;\n" :: "r"(ad+16), "l"(as_+4)); \
    uint32_t bd = bDst + (ST)*BST*4u;                                              \
    const float* bs_ = outW + (long)((KT)*16 + kk)*Vv + v0 + vv;                   \
    asm volatile("cp.async.cg.shared.global [%0], [%1], 16;\n" :: "r"(bd), "l"(bs_)); \
    asm volatile("cp.async.cg.shared.global [%0], [%1], 16;\n" :: "r"(bd+16), "l"(bs_+4)); \
    asm volatile("cp.async.commit_group;\n");                                      \
} while (0)

    ISSUE(0, 0); ISSUE(1, 1);

    int st = 0, pst = 2;
    for (int kt = 0; kt < 32; kt++) {
        asm volatile("cp.async.wait_group 1;\n" ::: "memory");
        __syncthreads();
        if (kt + 2 < 32) ISSUE(pst, kt + 2);   // pst == (kt-1)%3: consumed last iter
        const uint32_t* A_ = Asm + st*AST;
        const uint32_t* B_ = Bsm + st*BST;
#pragma unroll
        for (int ks = 0; ks < 2; ks++) {
            uint32_t a[2][4];
#pragma unroll
            for (int mt = 0; mt < 2; mt++) {
                int m = wmA + mt*16;
                a[mt][0] = A_[(m+g   )*36 + ks*8 + i4    ];
                a[mt][1] = A_[(m+g+8 )*36 + ks*8 + i4    ];
                a[mt][2] = A_[(m+g   )*36 + ks*8 + i4 + 4];
                a[mt][3] = A_[(m+g+8 )*36 + ks*8 + i4 + 4];
            }
#pragma unroll
            for (int nt = 0; nt < 8; nt++) {
                uint32_t b0 = B_[(ks*8 + i4    )*136 + wnB + nt*8 + g];
                uint32_t b1 = B_[(ks*8 + i4 + 4)*136 + wnB + nt*8 + g];
#pragma unroll
                for (int mt = 0; mt < 2; mt++) {
                    asm volatile(
                        "mma.sync.aligned.m16n8k8.row.col.f32.tf32.tf32.f32 "
                        "{%0,%1,%2,%3}, {%4,%5,%6,%7}, {%8,%9}, {%0,%1,%2,%3};\n"
                        : "+f"(acc[mt][nt][0]), "+f"(acc[mt][nt][1]),
                          "+f"(acc[mt][nt][2]), "+f"(acc[mt][nt][3])
                        : "r"(a[mt][0]), "r"(a[mt][1]), "r"(a[mt][2]), "r"(a[mt][3]),
                          "r"(b0), "r"(b1));
                }
            }
        }
        __syncthreads();
        st  = (st  + 1 == NSTG) ? 0 : st  + 1;
        pst = (pst + 1 == NSTG) ? 0 : pst + 1;
    }
#undef ISSUE

    // epilogue: bias, store logits, fused partial log-softmax (per 64-col half)
    float ob0s[8], ob1s[8];
#pragma unroll
    for (int nt = 0; nt < 8; nt++) {
        int v = v0 + wnB + nt*8 + 2*i4;
        ob0s[nt] = outb[v]; ob1s[nt] = outb[v+1];
    }
    float mx[2][2] = {{-1e30f,-1e30f},{-1e30f,-1e30f}};
#pragma unroll
    for (int mt = 0; mt < 2; mt++) {
        long ro = (long)(wmA + mt*16 + g)*Vv;
#pragma unroll
        for (int nt = 0; nt < 8; nt++) {
            int v = v0 + wnB + nt*8 + 2*i4;
            float r0 = acc[mt][nt][0]+ob0s[nt], r1 = acc[mt][nt][1]+ob1s[nt];
            float r2 = acc[mt][nt][2]+ob0s[nt], r3 = acc[mt][nt][3]+ob1s[nt];
            *(float2*)(out + ro + v)          = make_float2(r0, r1);
            *(float2*)(out + ro + 8L*Vv + v)  = make_float2(r2, r3);
            mx[mt][0] = fmaxf(mx[mt][0], fmaxf(r0, r1));
            mx[mt][1] = fmaxf(mx[mt][1], fmaxf(r2, r3));
        }
    }
    float ss[2][2] = {{0.f,0.f},{0.f,0.f}};
#pragma unroll
    for (int mt = 0; mt < 2; mt++)
#pragma unroll
        for (int nt = 0; nt < 8; nt++) {
            ss[mt][0] += __expf(acc[mt][nt][0]+ob0s[nt]-mx[mt][0])
                       + __expf(acc[mt][nt][1]+ob1s[nt]-mx[mt][0]);
            ss[mt][1] += __expf(acc[mt][nt][2]+ob0s[nt]-mx[mt][1])
                       + __expf(acc[mt][nt][3]+ob1s[nt]-mx[mt][1]);
        }
#pragma unroll
    for (int o = 1; o <= 2; o <<= 1) {
#pragma unroll
        for (int mt = 0; mt < 2; mt++)
#pragma unroll
            for (int hh = 0; hh < 2; hh++) {
                float om = __shfl_xor_sync(0xffffffffu, mx[mt][hh], o);
                float os = __shfl_xor_sync(0xffffffffu, ss[mt][hh], o);
                float nm = fmaxf(mx[mt][hh], om);
                ss[mt][hh] = ss[mt][hh]*__expf(mx[mt][hh]-nm) + os*__expf(om-nm);
                mx[mt][hh] = nm;
            }
    }
    if (i4 == 0) {
        int pc = blk*2 + (w & 1);
#pragma unroll
        for (int mt = 0; mt < 2; mt++)
#pragma unroll
            for (int hh = 0; hh < 2; hh++) {
                int row = wmA + mt*16 + g + hh*8;
                g_pM[row*NP + pc] = mx[mt][hh];
                g_pL[row*NP + pc] = ss[mt][hh];
            }
    }
}

// ---------------- K5a: merge partials -> g_lse[b] ---------------------------
__global__ void __launch_bounds__(256) lse_merge() {
    __shared__ float redm[8], reds[8];
    int b = blockIdx.x, tid = threadIdx.x;
    float m = -1e30f, l = 0.f;
    for (int p = tid; p < NP; p += 256) {
        float pm = g_pM[b*NP + p], pl = g_pL[b*NP + p];
        float nm = fmaxf(m, pm);
        l = l*__expf(m-nm) + pl*__expf(pm-nm);
        m = nm;
    }
#pragma unroll
    for (int o = 16; o; o >>= 1) {
        float om = __shfl_xor_sync(0xffffffffu, m, o);
        float ol = __shfl_xor_sync(0xffffffffu, l, o);
        float nm = fmaxf(m, om);
        l = l*__expf(m-nm) + ol*__expf(om-nm);
        m = nm;
    }
    if ((tid & 31) == 0) { redm[tid>>5] = m; reds[tid>>5] = l; }
    __syncthreads();
    if (tid == 0) {
        float M = -1e30f, L = 0.f;
        for (int i = 0; i < 8; i++) {
            float nm = fmaxf(M, redm[i]);
            L = L*__expf(M-nm) + reds[i]*__expf(redm[i]-nm);
            M = nm;
        }
        g_lse[b] = M + logf(L);
    }
}

// ---------------- K5b: subtract lse (512 blocks, quarter-row each) ----------
__global__ void __launch_bounds__(256) lse_sub(float* __restrict__ out) {
    int b = blockIdx.x >> 2, q = blockIdx.x & 3;
    int tid = threadIdx.x;
    float lse = g_lse[b];
    float4* row = (float4*)(out + (long)b*Vv) + q*2000;
    for (int t = tid; t < 2000; t += 256) {
        float4 x = row[t];
        x.x -= lse; x.y -= lse; x.z -= lse; x.w -= lse;
        row[t] = x;
    }
}

// ---------------- launch ---------------------------------------------------
extern "C" void kernel_launch(void* const* d_in, const int* in_sizes, int n_in,
                              void* d_out, int out_size) {
    (void)in_sizes; (void)n_in; (void)out_size;
    const int*   ids    = (const int*)  d_in[0];
    const float* hidden = (const float*)d_in[1];
    const float* enc    = (const float*)d_in[2];
    const float* emb    = (const float*)d_in[3];
    const float* attnW  = (const float*)d_in[4];
    // d_in[5] = attn_b: per-batch constant in softmax argument — cancels.
    const float* W_ih   = (const float*)d_in[6];
    const float* W_hh   = (const float*)d_in[7];
    const float* b_ih   = (const float*)d_in[8];
    const float* b_hh   = (const float*)d_in[9];
    const float* outW   = (const float*)d_in[10];
    const float* outb   = (const float*)d_in[11];
    float* out = (float*)d_out;

    static bool attr_done = false;
    if (!attr_done) {
        cudaFuncSetAttribute(gemm_logits,
                             cudaFuncAttributeMaxDynamicSharedMemorySize, SMEMB);
        attr_done = true;
    }

    q_kernel<<<Bb, 256>>>(hidden, attnW);
    attn_partial<<<dim3(7, Bb), 512>>>(enc, outW, W_ih, W_hh);
    attn_combine<<<Bb, 256>>>(ids, emb, out);
    gates_mma<<<dim3(24, 2, 4), 256>>>(hidden, W_ih, W_hh);
    gru_kernel<<<Bb, 256>>>(hidden, b_ih, b_hh, out);
    gemm_logits<<<NBLK, 256, SMEMB>>>(outW, outb, out);
    lse_merge<<<Bb, 256>>>();
    lse_sub<<<Bb*4, 256>>>(out);
}

// round 14
// speedup vs baseline: 4.6073x; 1.1150x over previous
#include <cuda_runtime.h>
#include <cuda_bf16.h>
#include <cstdint>

#define Vv 32000
#define Hh 256
#define Ss 2048
#define Bb 128
#define BV (Bb*Vv)
#define NBLK 250           // gemm_logits blocks
#define NP   (NBLK*2)      // partial-softmax columns per row (2 n-halves/block)

// gemm_logits smem: 4 stages * (A 128x12 + B 16x132) words
#define ASTw 1536          // words per A stage (128*12) — bf16 pairs, stride 12
#define BSTw 2112          // words per B stage (16*132) — fp32, stride 132
#define NSTG 4
#define SMEMB (NSTG*(ASTw+BSTw)*4)

// ---------------- scratch (static __device__, no allocation) ----------------
__device__ float g_q[Bb*Hh];
__device__ float g_ctx[Bb*Hh];
__device__ float g_xcat[Bb*512];
__device__ float g_scores[Bb*Ss];
__device__ float g_partM[Bb*4];
__device__ float g_partL[Bb*4];
__device__ float g_ctxPart[Bb*4*Hh];
__device__ float g_gAp[4*Bb*768];   // split-K partials (no bias)
__device__ float g_gBp[4*Bb*768];
__device__ float g_pM[Bb*NP];       // per-block logit max partials
__device__ float g_pL[Bb*NP];       // per-block sumexp partials
__device__ __align__(16) uint32_t g_catB[Bb*256];   // [h_new, ctx] as packed bf16x2

__device__ __forceinline__ uint32_t tf32u(float x) {
    uint32_t u;
    asm("cvt.rna.tf32.f32 %0, %1;" : "=r"(u) : "f"(x));
    return u;
}

__device__ __forceinline__ uint32_t bf16pack(float lo, float hi) {
    uint32_t r;
    asm("cvt.rn.bf16x2.f32 %0, %1, %2;" : "=r"(r) : "f"(hi), "f"(lo));
    return r;
}

__device__ __forceinline__ void l2_prefetch(const void* p) {
    asm volatile("prefetch.global.L2 [%0];" :: "l"(p));
}

// ---------------- K0: q[b,h] = sum_k h[b,k] * We[k,h]  (We = attn_W[:,H:]) ----
__global__ void __launch_bounds__(256) q_kernel(const float* __restrict__ hidden,
                                                const float* __restrict__ attnW) {
    int b = blockIdx.x, h = threadIdx.x;
    __shared__ float hs[Hh];
    hs[h] = hidden[b*Hh + h];
    __syncthreads();
    float acc = 0.f;
#pragma unroll 8
    for (int k = 0; k < Hh; k++) acc += hs[k] * attnW[k*(2*Hh) + Hh + h];
    g_q[b*Hh + h] = acc;
}

// ---------------- K1a: flash attention partials + L2 prefetch of weights ----
__global__ void __launch_bounds__(512) attn_partial(const float* __restrict__ enc,
        const float* __restrict__ outW, const float* __restrict__ W_ih,
        const float* __restrict__ W_hh) {
    int b = blockIdx.y, sc = blockIdx.x;
    int tid = threadIdx.x;

    if (sc >= 4) {
        if (sc < 6) {
            int pid = (sc - 4)*Bb + b;
            const float* src = outW + (long)pid*64000;
            for (int t = tid; t < 2000; t += 512)
                l2_prefetch(src + t*32);
        } else {
            const float* s1 = W_ih + (long)b*3072;
            for (int t = tid; t < 96; t += 512)
                l2_prefetch(s1 + t*32);
            const float* s2 = W_hh + (long)b*1536;
            for (int t = tid; t < 48; t += 512)
                l2_prefetch(s2 + t*32);
        }
        return;
    }

    int w = tid >> 5, lane = tid & 31;
    __shared__ float qs[Hh];
    __shared__ float wm[16], wl[16];
    __shared__ float wctx[16][Hh];
    if (tid < Hh) qs[tid] = g_q[b*Hh + tid];
    __syncthreads();
    float qv[8];
#pragma unroll
    for (int k = 0; k < 8; k++) qv[k] = qs[lane*8 + k];

    const float* encb = enc + (long)b*Hh + (long)sc*512*(Bb*Hh) + lane*8;
    float m = -1e30f, l = 0.f;
    float c[8];
#pragma unroll
    for (int k = 0; k < 8; k++) c[k] = 0.f;

    for (int j0 = 0; j0 < 32; j0 += 4) {
        float e[4][8];
#pragma unroll
        for (int jj = 0; jj < 4; jj++) {
            const float* p = encb + (long)(w + 16*(j0+jj))*(Bb*Hh);
            float4 x0 = __ldcs((const float4*)p);
            float4 x1 = __ldcs((const float4*)(p+4));
            e[jj][0]=x0.x; e[jj][1]=x0.y; e[jj][2]=x0.z; e[jj][3]=x0.w;
            e[jj][4]=x1.x; e[jj][5]=x1.y; e[jj][6]=x1.z; e[jj][7]=x1.w;
        }
#pragma unroll
        for (int jj = 0; jj < 4; jj++) {
            float part = 0.f;
#pragma unroll
            for (int k = 0; k < 8; k++) part += e[jj][k]*qv[k];
#pragma unroll
            for (int o = 16; o; o >>= 1) part += __shfl_xor_sync(0xffffffffu, part, o);
            if (lane == 0) g_scores[b*Ss + sc*512 + w + 16*(j0+jj)] = part;
            float nm  = fmaxf(m, part);
            float scl = __expf(m - nm);
            float p_  = __expf(part - nm);
            l = l*scl + p_;
#pragma unroll
            for (int k = 0; k < 8; k++) c[k] = c[k]*scl + p_*e[jj][k];
            m = nm;
        }
    }
    if (lane == 0) { wm[w] = m; wl[w] = l; }
#pragma unroll
    for (int k = 0; k < 8; k++) wctx[w][lane*8+k] = c[k];
    __syncthreads();
    if (tid < Hh) {
        float gm = -1e30f;
        for (int i = 0; i < 16; i++) gm = fmaxf(gm, wm[i]);
        float L = 0.f, cv = 0.f;
        for (int i = 0; i < 16; i++) {
            float f = __expf(wm[i] - gm);
            L  += wl[i]*f;
            cv += wctx[i][tid]*f;
        }
        g_ctxPart[(b*4+sc)*Hh + tid] = cv;
        if (tid == 0) { g_partM[b*4+sc] = gm; g_partL[b*4+sc] = L; }
    }
}

// ---------------- K1b: combine partials, write attn_weights + context + xcat
__global__ void __launch_bounds__(256) attn_combine(const int* __restrict__ ids,
                                                    const float* __restrict__ emb,
                                                    float* __restrict__ out) {
    int b = blockIdx.x, tid = threadIdx.x;
    float m0 = g_partM[b*4+0], m1 = g_partM[b*4+1], m2 = g_partM[b*4+2], m3 = g_partM[b*4+3];
    float gm = fmaxf(fmaxf(m0,m1), fmaxf(m2,m3));
    float f0 = __expf(m0-gm), f1 = __expf(m1-gm), f2 = __expf(m2-gm), f3 = __expf(m3-gm);
    float L = g_partL[b*4+0]*f0 + g_partL[b*4+1]*f1 + g_partL[b*4+2]*f2 + g_partL[b*4+3]*f3;
    float cv = g_ctxPart[(b*4+0)*Hh+tid]*f0 + g_ctxPart[(b*4+1)*Hh+tid]*f1
             + g_ctxPart[(b*4+2)*Hh+tid]*f2 + g_ctxPart[(b*4+3)*Hh+tid]*f3;
    float ctx = cv / L;
    g_ctx[b*Hh + tid] = ctx;
    g_xcat[b*512 + tid]       = emb[(long)ids[b]*Hh + tid];
    g_xcat[b*512 + 256 + tid] = ctx;
    float invL = 1.f / L;
    for (int s = tid; s < Ss; s += 256)
        out[BV + Bb*Hh + b*Ss + s] = __expf(g_scores[b*Ss+s] - gm) * invL;
}

// ---------------- K2: gates TF32 GEMM, split-K x4 ---------------------------
__global__ void __launch_bounds__(256) gates_mma(const float* __restrict__ hidden,
        const float* __restrict__ W_ih, const float* __restrict__ W_hh) {
    __shared__ uint32_t As[2][128*36];
    __shared__ uint32_t Bs[2][32*36];

    int phase = blockIdx.y, z = blockIdx.z;
    const float* SRC  = phase ? hidden : g_xcat;
    const float* WPTR = phase ? W_hh   : W_ih;
    float*       dst  = (phase ? g_gBp : g_gAp) + z*(Bb*768);
    int LD = phase ? 256 : 512;
    int KT = phase ? 2   : 4;
    int kbase = z * KT * 32;

    int n0  = blockIdx.x * 32;
    int tid = threadIdx.x;
    int w = tid >> 5, lane = tid & 31;
    int wm = (w >> 1) * 32, wn = (w & 1) * 16;
    int g = lane >> 2, i4 = lane & 3;

    int arow = tid >> 3, acol = (tid & 7) * 4;
    int brow = tid >> 3, bcol = (tid & 7) * 4;

    float accA[2][2][4];
#pragma unroll
    for (int mt = 0; mt < 2; mt++)
#pragma unroll
        for (int nt = 0; nt < 2; nt++)
#pragma unroll
            for (int c = 0; c < 4; c++) accA[mt][nt][c] = 0.f;

    float4 ra[4]; float4 rb;
#pragma unroll
    for (int it = 0; it < 4; it++)
        ra[it] = *(const float4*)(SRC + (long)(arow + it*32)*LD + kbase + acol);
    rb = *(const float4*)(WPTR + (long)(n0 + brow)*LD + kbase + bcol);
#pragma unroll
    for (int it = 0; it < 4; it++) {
        int r = arow + it*32;
        As[0][r*36+acol+0] = tf32u(ra[it].x); As[0][r*36+acol+1] = tf32u(ra[it].y);
        As[0][r*36+acol+2] = tf32u(ra[it].z); As[0][r*36+acol+3] = tf32u(ra[it].w);
    }
    Bs[0][brow*36+bcol+0] = tf32u(rb.x); Bs[0][brow*36+bcol+1] = tf32u(rb.y);
    Bs[0][brow*36+bcol+2] = tf32u(rb.z); Bs[0][brow*36+bcol+3] = tf32u(rb.w);
    __syncthreads();

    for (int kt = 0; kt < KT; kt++) {
        int cur = kt & 1;
        if (kt + 1 < KT) {
            int k0 = kbase + (kt + 1) * 32;
#pragma unroll
            for (int it = 0; it < 4; it++)
                ra[it] = *(const float4*)(SRC + (long)(arow + it*32)*LD + k0 + acol);
            rb = *(const float4*)(WPTR + (long)(n0 + brow)*LD + k0 + bcol);
        }
#pragma unroll
        for (int ks = 0; ks < 4; ks++) {
            uint32_t a[2][4];
#pragma unroll
            for (int mt = 0; mt < 2; mt++) {
                int m = wm + mt*16;
                a[mt][0] = As[cur][(m+g   )*36 + ks*8 + i4    ];
                a[mt][1] = As[cur][(m+g+8 )*36 + ks*8 + i4    ];
                a[mt][2] = As[cur][(m+g   )*36 + ks*8 + i4 + 4];
                a[mt][3] = As[cur][(m+g+8 )*36 + ks*8 + i4 + 4];
            }
#pragma unroll
            for (int nt = 0; nt < 2; nt++) {
                uint32_t b0 = Bs[cur][(wn+nt*8+g)*36 + ks*8 + i4    ];
                uint32_t b1 = Bs[cur][(wn+nt*8+g)*36 + ks*8 + i4 + 4];
#pragma unroll
                for (int mt = 0; mt < 2; mt++) {
                    asm volatile(
                        "mma.sync.aligned.m16n8k8.row.col.f32.tf32.tf32.f32 "
                        "{%0,%1,%2,%3}, {%4,%5,%6,%7}, {%8,%9}, {%0,%1,%2,%3};\n"
                        : "+f"(accA[mt][nt][0]), "+f"(accA[mt][nt][1]),
                          "+f"(accA[mt][nt][2]), "+f"(accA[mt][nt][3])
                        : "r"(a[mt][0]), "r"(a[mt][1]), "r"(a[mt][2]), "r"(a[mt][3]),
                          "r"(b0), "r"(b1));
                }
            }
        }
        if (kt + 1 < KT) {
            int nxt = 1 - cur;
#pragma unroll
            for (int it = 0; it < 4; it++) {
                int r = arow + it*32;
                As[nxt][r*36+acol+0] = tf32u(ra[it].x); As[nxt][r*36+acol+1] = tf32u(ra[it].y);
                As[nxt][r*36+acol+2] = tf32u(ra[it].z); As[nxt][r*36+acol+3] = tf32u(ra[it].w);
            }
            Bs[nxt][brow*36+bcol+0] = tf32u(rb.x); Bs[nxt][brow*36+bcol+1] = tf32u(rb.y);
            Bs[nxt][brow*36+bcol+2] = tf32u(rb.z); Bs[nxt][brow*36+bcol+3] = tf32u(rb.w);
        }
        __syncthreads();
    }

#pragma unroll
    for (int mt = 0; mt < 2; mt++) {
        int m = wm + mt*16 + g;
#pragma unroll
        for (int nt = 0; nt < 2; nt++) {
            int n = n0 + wn + nt*8 + 2*i4;
            dst[(m  )*768 + n  ] = accA[mt][nt][0];
            dst[(m  )*768 + n+1] = accA[mt][nt][1];
            dst[(m+8)*768 + n  ] = accA[mt][nt][2];
            dst[(m+8)*768 + n+1] = accA[mt][nt][3];
        }
    }
}

// ---------------- K3: GRU combine, emits packed bf16 cat pairs --------------
__global__ void __launch_bounds__(256) gru_kernel(const float* __restrict__ hidden,
        const float* __restrict__ b_ih, const float* __restrict__ b_hh,
        float* __restrict__ out) {
    __shared__ float cat[512];
    int b = blockIdx.x, t = threadIdx.x;
#define SUM4(P, IDX) (P[IDX] + P[(Bb*768)+(IDX)] + P[2*(Bb*768)+(IDX)] + P[3*(Bb*768)+(IDX)])
    int i0 = b*768 + t, i1 = i0 + 256, i2 = i0 + 512;
    float Ar = SUM4(g_gAp, i0) + b_ih[t];
    float Az = SUM4(g_gAp, i1) + b_ih[256+t];
    float An = SUM4(g_gAp, i2) + b_ih[512+t];
    float Br = SUM4(g_gBp, i0) + b_hh[t];
    float Bz = SUM4(g_gBp, i1) + b_hh[256+t];
    float Bn = SUM4(g_gBp, i2) + b_hh[512+t];
#undef SUM4
    float r  = 1.f/(1.f + __expf(-(Ar+Br)));
    float z  = 1.f/(1.f + __expf(-(Az+Bz)));
    float n  = tanhf(An + r*Bn);
    float h  = hidden[b*Hh + t];
    float hn = (1.f - z)*n + z*h;
    out[BV + b*Hh + t] = hn;
    float ctx = g_ctx[b*Hh + t];
    cat[t]       = hn;
    cat[256 + t] = ctx;
    __syncthreads();
    g_catB[b*256 + t] = bf16pack(cat[2*t], cat[2*t+1]);
}

// ---------------- K4: logits bf16 GEMM, cp.async 4-stage, 1 sync/tile -------
// Block: 128(v) x 128(m); 8 warps = 4(m) x 2(n); per-warp 32m x 64v.
// A: packed bf16 pairs via cp.async. B: fp32 [k][v] via cp.async, converted
// to bf16x2 during fragment build (fma pipe).
__global__ void __launch_bounds__(256, 2) gemm_logits(const float* __restrict__ outW,
        const float* __restrict__ outb, float* __restrict__ out) {
    extern __shared__ uint32_t sm[];
    uint32_t* Asm = sm;               // NSTG stages x ASTw (bf16 pairs, stride 12)
    uint32_t* Bsm = sm + NSTG*ASTw;   // NSTG stages x BSTw (fp32, stride 132)

    int blk = blockIdx.x;
    int v0  = blk * 128;
    int tid = threadIdx.x;
    int w = tid >> 5, lane = tid & 31;
    int g = lane >> 2, i4 = lane & 3;
    int wmA = (w >> 1) * 32;
    int wnB = (w & 1) * 64;

    int arow = tid >> 1, ahalf = tid & 1;   // A: 128 rows x 2 16B-chunks
    int kk = tid >> 4, vv = (tid & 15)*8;   // B: 16 k-rows x (2x16B per thread)

    float acc[2][8][4];
#pragma unroll
    for (int mt = 0; mt < 2; mt++)
#pragma unroll
        for (int nt = 0; nt < 8; nt++)
#pragma unroll
            for (int c = 0; c < 4; c++) acc[mt][nt][c] = 0.f;

    uint32_t aDst = (uint32_t)__cvta_generic_to_shared(Asm) + (arow*12 + ahalf*4)*4u;
    uint32_t bDst = (uint32_t)__cvta_generic_to_shared(Bsm) + (kk*132 + vv)*4u;
    const uint32_t* aSrc = g_catB + arow*256 + ahalf*4;

#define ISSUE(ST, KT) do {                                                         \
    uint32_t ad = aDst + (ST)*ASTw*4u;                                             \
    const uint32_t* as_ = aSrc + (KT)*8;                                           \
    asm volatile("cp.async.cg.shared.global [%0], [%1], 16;\n" :: "r"(ad), "l"(as_)); \
    uint32_t bd = bDst + (ST)*BSTw*4u;                                             \
    const float* bs_ = outW + (long)((KT)*16 + kk)*Vv + v0 + vv;                   \
    asm volatile("cp.async.cg.shared.global [%0], [%1], 16;\n" :: "r"(bd), "l"(bs_)); \
    asm volatile("cp.async.cg.shared.global [%0], [%1], 16;\n" :: "r"(bd+16), "l"(bs_+4)); \
    asm volatile("cp.async.commit_group;\n");                                      \
} while (0)

    ISSUE(0, 0); ISSUE(1, 1); ISSUE(2, 2);

    for (int kt = 0; kt < 32; kt++) {
        int st = kt & 3;
        asm volatile("cp.async.wait_group 2;\n" ::: "memory");
        __syncthreads();
        if (kt + 3 < 32) ISSUE((kt + 3) & 3, kt + 3);
        else asm volatile("cp.async.commit_group;\n");   // keep group count stable
        const uint32_t* A_ = Asm + st*ASTw;
        const float*    B_ = (const float*)(Bsm + st*BSTw);
        uint32_t a[2][4];
#pragma unroll
        for (int mt = 0; mt < 2; mt++) {
            int m = wmA + mt*16;
            a[mt][0] = A_[(m+g   )*12 + i4    ];
            a[mt][1] = A_[(m+g+8 )*12 + i4    ];
            a[mt][2] = A_[(m+g   )*12 + i4 + 4];
            a[mt][3] = A_[(m+g+8 )*12 + i4 + 4];
        }
#pragma unroll
        for (int nt = 0; nt < 8; nt++) {
            int vr = wnB + nt*8 + g;
            float f0 = B_[(2*i4    )*132 + vr];
            float f1 = B_[(2*i4 + 1)*132 + vr];
            float f2 = B_[(2*i4 + 8)*132 + vr];
            float f3 = B_[(2*i4 + 9)*132 + vr];
            uint32_t b0 = bf16pack(f0, f1);
            uint32_t b1 = bf16pack(f2, f3);
#pragma unroll
            for (int mt = 0; mt < 2; mt++) {
                asm volatile(
                    "mma.sync.aligned.m16n8k16.row.col.f32.bf16.bf16.f32 "
                    "{%0,%1,%2,%3}, {%4,%5,%6,%7}, {%8,%9}, {%0,%1,%2,%3};\n"
                    : "+f"(acc[mt][nt][0]), "+f"(acc[mt][nt][1]),
                      "+f"(acc[mt][nt][2]), "+f"(acc[mt][nt][3])
                    : "r"(a[mt][0]), "r"(a[mt][1]), "r"(a[mt][2]), "r"(a[mt][3]),
                      "r"(b0), "r"(b1));
            }
        }
    }
#undef ISSUE

    // epilogue: bias, store logits, fused partial log-softmax (per 64-col half)
    float ob0s[8], ob1s[8];
#pragma unroll
    for (int nt = 0; nt < 8; nt++) {
        int v = v0 + wnB + nt*8 + 2*i4;
        ob0s[nt] = outb[v]; ob1s[nt] = outb[v+1];
    }
    float mx[2][2] = {{-1e30f,-1e30f},{-1e30f,-1e30f}};
#pragma unroll
    for (int mt = 0; mt < 2; mt++) {
        long ro = (long)(wmA + mt*16 + g)*Vv;
#pragma unroll
        for (int nt = 0; nt < 8; nt++) {
            int v = v0 + wnB + nt*8 + 2*i4;
            float r0 = acc[mt][nt][0]+ob0s[nt], r1 = acc[mt][nt][1]+ob1s[nt];
            float r2 = acc[mt][nt][2]+ob0s[nt], r3 = acc[mt][nt][3]+ob1s[nt];
            *(float2*)(out + ro + v)          = make_float2(r0, r1);
            *(float2*)(out + ro + 8L*Vv + v)  = make_float2(r2, r3);
            mx[mt][0] = fmaxf(mx[mt][0], fmaxf(r0, r1));
            mx[mt][1] = fmaxf(mx[mt][1], fmaxf(r2, r3));
        }
    }
    float ss[2][2] = {{0.f,0.f},{0.f,0.f}};
#pragma unroll
    for (int mt = 0; mt < 2; mt++)
#pragma unroll
        for (int nt = 0; nt < 8; nt++) {
            ss[mt][0] += __expf(acc[mt][nt][0]+ob0s[nt]-mx[mt][0])
                       + __expf(acc[mt][nt][1]+ob1s[nt]-mx[mt][0]);
            ss[mt][1] += __expf(acc[mt][nt][2]+ob0s[nt]-mx[mt][1])
                       + __expf(acc[mt][nt][3]+ob1s[nt]-mx[mt][1]);
        }
#pragma unroll
    for (int o = 1; o <= 2; o <<= 1) {
#pragma unroll
        for (int mt = 0; mt < 2; mt++)
#pragma unroll
            for (int hh = 0; hh < 2; hh++) {
                float om = __shfl_xor_sync(0xffffffffu, mx[mt][hh], o);
                float os = __shfl_xor_sync(0xffffffffu, ss[mt][hh], o);
                float nm = fmaxf(mx[mt][hh], om);
                ss[mt][hh] = ss[mt][hh]*__expf(mx[mt][hh]-nm) + os*__expf(om-nm);
                mx[mt][hh] = nm;
            }
    }
    if (i4 == 0) {
        int pc = blk*2 + (w & 1);
#pragma unroll
        for (int mt = 0; mt < 2; mt++)
#pragma unroll
            for (int hh = 0; hh < 2; hh++) {
                int row = wmA + mt*16 + g + hh*8;
                g_pM[row*NP + pc] = mx[mt][hh];
                g_pL[row*NP + pc] = ss[mt][hh];
            }
    }
}

// ---------------- K5: fused merge + subtract (512 blocks, quarter-row each) -
__global__ void __launch_bounds__(256) lse_sub(float* __restrict__ out) {
    __shared__ float redm[8], reds[8];
    __shared__ float s_lse;
    int b = blockIdx.x >> 2, q = blockIdx.x & 3;
    int tid = threadIdx.x;
    // merge the NP partials for row b (redundant across the 4 q-blocks; cheap)
    float m = -1e30f, l = 0.f;
    for (int p = tid; p < NP; p += 256) {
        float pm = g_pM[b*NP + p], pl = g_pL[b*NP + p];
        float nm = fmaxf(m, pm);
        l = l*__expf(m-nm) + pl*__expf(pm-nm);
        m = nm;
    }
#pragma unroll
    for (int o = 16; o; o >>= 1) {
        float om = __shfl_xor_sync(0xffffffffu, m, o);
        float ol = __shfl_xor_sync(0xffffffffu, l, o);
        float nm = fmaxf(m, om);
        l = l*__expf(m-nm) + ol*__expf(om-nm);
        m = nm;
    }
    if ((tid & 31) == 0) { redm[tid>>5] = m; reds[tid>>5] = l; }
    __syncthreads();
    if (tid == 0) {
        float M = -1e30f, L = 0.f;
        for (int i = 0; i < 8; i++) {
            float nm = fmaxf(M, redm[i]);
            L = L*__expf(M-nm) + reds[i]*__expf(redm[i]-nm);
            M = nm;
        }
        s_lse = M + logf(L);
    }
    __syncthreads();
    float lse = s_lse;
    float4* row = (float4*)(out + (long)b*Vv) + q*2000;
    for (int t = tid; t < 2000; t += 256) {
        float4 x = row[t];
        x.x -= lse; x.y -= lse; x.z -= lse; x.w -= lse;
        row[t] = x;
    }
}

// ---------------- launch ---------------------------------------------------
extern "C" void kernel_launch(void* const* d_in, const int* in_sizes, int n_in,
                              void* d_out, int out_size) {
    (void)in_sizes; (void)n_in; (void)out_size;
    const int*   ids    = (const int*)  d_in[0];
    const float* hidden = (const float*)d_in[1];
    const float* enc    = (const float*)d_in[2];
    const float* emb    = (const float*)d_in[3];
    const float* attnW  = (const float*)d_in[4];
    // d_in[5] = attn_b: per-batch constant in softmax argument — cancels.
    const float* W_ih   = (const float*)d_in[6];
    const float* W_hh   = (const float*)d_in[7];
    const float* b_ih   = (const float*)d_in[8];
    const float* b_hh   = (const float*)d_in[9];
    const float* outW   = (const float*)d_in[10];
    const float* outb   = (const float*)d_in[11];
    float* out = (float*)d_out;

    static bool attr_done = false;
    if (!attr_done) {
        cudaFuncSetAttribute(gemm_logits,
                             cudaFuncAttributeMaxDynamicSharedMemorySize, SMEMB);
        attr_done = true;
    }

    q_kernel<<<Bb, 256>>>(hidden, attnW);
    attn_partial<<<dim3(7, Bb), 512>>>(enc, outW, W_ih, W_hh);
    attn_combine<<<Bb, 256>>>(ids, emb, out);
    gates_mma<<<dim3(24, 2, 4), 256>>>(hidden, W_ih, W_hh);
    gru_kernel<<<Bb, 256>>>(hidden, b_ih, b_hh, out);
    gemm_logits<<<NBLK, 256, SMEMB>>>(outW, outb, out);
    lse_sub<<<Bb*4, 256>>>(out);
}